// round 6
// baseline (speedup 1.0000x reference)
#include <cuda_runtime.h>
#include <math.h>

#define NB 2
#define LL 9216
#define NHH 4
#define CHK 144
#define NCHK 64
#define TOKS (NB*LL)

// ---------------- static scratch ----------------
__device__ float g_xe[TOKS*16];
__device__ float g_xm[TOKS*16];
__device__ float g_ye[(size_t)TOKS*64];
__device__ float g_fe[(size_t)TOKS*64];
__device__ float g_H [(size_t)TOKS*144];
__device__ unsigned char g_code[NB*NHH*LL];
__device__ int   g_perm[NB*NHH*LL];
__device__ float g_bsc[NB*NHH*LL];
__device__ float g_ret[(size_t)NB*NHH*LL*64];

// =======================================================================
// K1: fused 3x3 SAME conv (144 out ch) + ReLU -> xe(16), ye(64), fe(64)
// grid (96=y, 2=n, 2=co-half), block (96, 3)
// =======================================================================
__global__ __launch_bounds__(288) void conv_kernel(
    const float* __restrict__ x,
    const float* __restrict__ wm, const float* __restrict__ bm,
    const float* __restrict__ wa, const float* __restrict__ ba,
    const float* __restrict__ wf, const float* __restrict__ bf)
{
    __shared__ float in_sh[8][3][100];
    __shared__ float w_sh[8][72][12];

    const int y    = blockIdx.x;
    const int n    = blockIdx.y;
    const int half = blockIdx.z;
    const int xcol = threadIdx.x;          // 0..95
    const int lane = threadIdx.y;          // 0..2
    const int tid  = xcol + 96*lane;       // 0..287
    const int coBase = half*72;

    float acc[24];
#pragma unroll
    for (int m = 0; m < 24; ++m) acc[m] = 0.f;

    for (int cb = 0; cb < 8; ++cb) {
        __syncthreads();
        for (int idx = tid; idx < 8*3*98; idx += 288) {
            int c = idx / 294, rem = idx % 294, r = rem / 98, xx = rem % 98;
            int gy = y - 1 + r, gx = xx - 1, ci = cb*8 + c;
            float v = 0.f;
            if (gy >= 0 && gy < 96 && gx >= 0 && gx < 96)
                v = x[((n*64 + ci)*96 + gy)*96 + gx];
            in_sh[c][r][xx] = v;
        }
        for (int idx = tid; idx < 8*72*9; idx += 288) {
            int c = idx / 648, rem = idx % 648, co_l = rem / 9, tap = rem % 9;
            int co = coBase + co_l, ci = cb*8 + c;
            float w;
            if (co < 16)      w = wm[( co      *64 + ci)*9 + tap];
            else if (co < 80) w = wa[((co-16)*64 + ci)*9 + tap];
            else              w = wf[((co-80)*64 + ci)*9 + tap];
            w_sh[c][co_l][tap] = w;
        }
        __syncthreads();
#pragma unroll
        for (int c = 0; c < 8; ++c) {
            float i00 = in_sh[c][0][xcol], i01 = in_sh[c][0][xcol+1], i02 = in_sh[c][0][xcol+2];
            float i10 = in_sh[c][1][xcol], i11 = in_sh[c][1][xcol+1], i12 = in_sh[c][1][xcol+2];
            float i20 = in_sh[c][2][xcol], i21 = in_sh[c][2][xcol+1], i22 = in_sh[c][2][xcol+2];
#pragma unroll
            for (int m = 0; m < 24; ++m) {
                int co_l = lane*24 + m;
                float4 wa4 = *(const float4*)&w_sh[c][co_l][0];
                float4 wb4 = *(const float4*)&w_sh[c][co_l][4];
                float4 wc4 = *(const float4*)&w_sh[c][co_l][8];
                acc[m] += i00*wa4.x + i01*wa4.y + i02*wa4.z
                        + i10*wa4.w + i11*wb4.x + i12*wb4.y
                        + i20*wb4.z + i21*wb4.w + i22*wc4.x;
            }
        }
    }

    const int tok = n*LL + y*96 + xcol;
#pragma unroll
    for (int m = 0; m < 24; ++m) {
        int co = coBase + lane*24 + m;
        if (co < 16) {
            g_xe[tok*16 + co] = fmaxf(acc[m] + bm[co], 0.f);
        } else if (co < 80) {
            g_ye[(size_t)tok*64 + (co-16)] = fmaxf(acc[m] + ba[co-16], 0.f);
        } else {
            g_fe[(size_t)tok*64 + (co-80)] = fmaxf(acc[m] + bf[co-80], 0.f);
        }
    }
}

// =======================================================================
// K2: LSH codes (argmax over 64 rotated dirs per head) + normalized xm
// =======================================================================
__global__ __launch_bounds__(256) void code_kernel(const float* __restrict__ rot)
{
    __shared__ float rotT[4096];   // [(h*64+i)*16 + f]
    const int tid = threadIdx.x;
    for (int idx = tid; idx < 4096; idx += 256) {
        int hi = idx >> 4, f = idx & 15;
        rotT[idx] = rot[f*256 + hi];     // rot (16, 4, 64)
    }
    __syncthreads();

    const int tg = blockIdx.x*256 + tid;  // global token
    const int n = tg / LL, t = tg % LL;
    const float4* e = (const float4*)&g_xe[tg*16];
    float4 e0 = e[0], e1 = e[1], e2 = e[2], e3 = e[3];
    float ss = e0.x*e0.x+e0.y*e0.y+e0.z*e0.z+e0.w*e0.w
             + e1.x*e1.x+e1.y*e1.y+e1.z*e1.z+e1.w*e1.w
             + e2.x*e2.x+e2.y*e2.y+e2.z*e2.z+e2.w*e2.w
             + e3.x*e3.x+e3.y*e3.y+e3.z*e3.z+e3.w*e3.w;
    float inv = 1.f / fmaxf(sqrtf(ss), 5e-5f);
    float4* xmv = (float4*)&g_xm[tg*16];
    float4 m0=e0,m1=e1,m2=e2,m3=e3;
    m0.x*=inv; m0.y*=inv; m0.z*=inv; m0.w*=inv;
    m1.x*=inv; m1.y*=inv; m1.z*=inv; m1.w*=inv;
    m2.x*=inv; m2.y*=inv; m2.z*=inv; m2.w*=inv;
    m3.x*=inv; m3.y*=inv; m3.z*=inv; m3.w*=inv;
    xmv[0]=m0; xmv[1]=m1; xmv[2]=m2; xmv[3]=m3;

#pragma unroll
    for (int h = 0; h < 4; ++h) {
        float best = -1e30f; int bi = 0;
        for (int i = 0; i < 64; ++i) {
            const float4* rr = (const float4*)&rotT[(h*64+i)*16];
            float4 r0=rr[0],r1=rr[1],r2=rr[2],r3=rr[3];
            float d = e0.x*r0.x+e0.y*r0.y+e0.z*r0.z+e0.w*r0.w
                    + e1.x*r1.x+e1.y*r1.y+e1.z*r1.z+e1.w*r1.w
                    + e2.x*r2.x+e2.y*r2.y+e2.z*r2.z+e2.w*r2.w
                    + e3.x*r3.x+e3.y*r3.y+e3.z*r3.z+e3.w*r3.w;
            if (d > best) { best = d; bi = i; }
        }
        g_code[(n*4+h)*LL + t] = (unsigned char)bi;
    }
}

// =======================================================================
// K3: per-(n,h) stable counting sort over 64 buckets -> g_perm
// =======================================================================
__global__ __launch_bounds__(256) void sort_kernel()
{
    const int seg = blockIdx.x;            // 0..7
    __shared__ int hist[64];
    __shared__ int running[64];
    __shared__ int wh[8][64];
    const int tid = threadIdx.x;
    const int w = tid >> 5, ln = tid & 31;

    if (tid < 64) hist[tid] = 0;
    __syncthreads();
    const unsigned char* code = &g_code[seg*LL];
    for (int t = tid; t < LL; t += 256) atomicAdd(&hist[code[t]], 1);
    __syncthreads();
    if (tid == 0) {
        int acc = 0;
        for (int b = 0; b < 64; ++b) { running[b] = acc; acc += hist[b]; }
    }
    __syncthreads();

    for (int tile = 0; tile < 36; ++tile) {
        int t = tile*256 + tid;
        int c = code[t];
        unsigned mask = __match_any_sync(0xffffffffu, c);
        int lanerank = __popc(mask & ((1u << ln) - 1u));
        ((int*)wh)[tid] = 0; ((int*)wh)[tid + 256] = 0;
        __syncthreads();
        if (lanerank == 0) wh[w][c] = __popc(mask);
        __syncthreads();
        int r = lanerank;
        for (int w2 = 0; w2 < w; ++w2) r += wh[w2][c];
        int pos = running[c] + r;
        __syncthreads();
        if (tid < 64) {
            int s = 0;
            for (int w2 = 0; w2 < 8; ++w2) s += wh[w2][tid];
            running[tid] += s;
        }
        __syncthreads();
        g_perm[seg*LL + pos] = t;
    }
}

// =======================================================================
// K4: H = relu(fe @ fc1_w^T + fc1_b)  (token-level, computed ONCE)
// =======================================================================
__global__ __launch_bounds__(256) void hid_kernel(
    const float* __restrict__ fc1_w, const float* __restrict__ fc1_b)
{
    __shared__ float w_sh[144*64];
    __shared__ float fe_sh[16*64];
    __shared__ float b_sh[144];
    const int tid = threadIdx.x;
    for (int i = tid; i < 144*64; i += 256) w_sh[i] = fc1_w[i];
    if (tid < 144) b_sh[tid] = fc1_b[tid];
    const int tok0 = blockIdx.x * 16;
    for (int i = tid; i < 16*64; i += 256) fe_sh[i] = g_fe[(size_t)tok0*64 + i];
    __syncthreads();
#pragma unroll
    for (int k = 0; k < 9; ++k) {
        int o = tid + k*256;               // < 2304
        int tk = o / 144, col = o % 144;
        const float4* fv = (const float4*)&fe_sh[tk*64];
        const float4* wv = (const float4*)&w_sh[col*64];
        float s = 0.f;
#pragma unroll
        for (int q = 0; q < 16; ++q) {
            float4 a = fv[q], b = wv[q];
            s += a.x*b.x + a.y*b.y + a.z*b.z + a.w*b.w;
        }
        g_H[(size_t)(tok0+tk)*144 + col] = fmaxf(s + b_sh[col], 0.f);
    }
}

// =======================================================================
// K5: fused flash attention per (n,h,chunk). 432 keys = chunks {c,c-1,c+1}.
// logits = xs·xmatch + fc2_w[i]·H_j + fc2_b[i]. block (4,144): e-dim split 4x.
// =======================================================================
__global__ __launch_bounds__(576, 1) void attn_kernel(
    const float* __restrict__ fc2_w, const float* __restrict__ fc2_b)
{
    __shared__ float kf[48][160];   // [key][xm(16) | H(144)]
    __shared__ float ya[48][64];

    const int cblk = blockIdx.x;           // chunk
    const int h    = blockIdx.y;
    const int n    = blockIdx.z;
    const int seg  = n*4 + h;
    const int x4   = threadIdx.x;           // 0..3 (e-quarter)
    const int i    = threadIdx.y;           // 0..143 (query)
    const int tid  = x4 + 4*i;

    const int tq  = g_perm[seg*LL + cblk*CHK + i];   // local token
    const int tqg = n*LL + tq;                        // global token

    float q[40];
#pragma unroll
    for (int e = 0; e < 40; ++e) {
        int f = x4*40 + e;
        q[e] = (f < 16) ? g_xe[tqg*16 + f] : fc2_w[i*144 + (f-16)];
    }
    const float bcoef = fc2_b[i];

    float m = -1e30f, l = 0.f;
    float racc[16];
#pragma unroll
    for (int k = 0; k < 16; ++k) racc[k] = 0.f;

    for (int tilej = 0; tilej < 9; ++tilej) {
        const int j0 = tilej * 48;
        __syncthreads();
        for (int idx = tid; idx < 48*56; idx += 576) {
            int jj = idx / 56, comp = idx % 56;
            int j = j0 + jj;
            int jb = j / 144, jr = j % 144;
            int cc = cblk + (jb == 1 ? -1 : (jb == 2 ? 1 : 0));
            cc = (cc + 64) & 63;
            int tk  = g_perm[seg*LL + cc*CHK + jr];
            int tkg = n*LL + tk;
            float4 v;
            if (comp < 4)       v = *(const float4*)&g_xm[tkg*16 + comp*4];
            else if (comp < 40) v = *(const float4*)&g_H[(size_t)tkg*144 + (comp-4)*4];
            else                v = *(const float4*)&g_ye[(size_t)tkg*64 + (comp-40)*4];
            if (comp < 40) *(float4*)&kf[jj][comp*4] = v;
            else           *(float4*)&ya[jj][(comp-40)*4] = v;
        }
        __syncthreads();

        for (int jt = 0; jt < 48; ++jt) {
            const float4* kv = (const float4*)&kf[jt][x4*40];
            float s = 0.f;
#pragma unroll
            for (int qi = 0; qi < 10; ++qi) {
                float4 b = kv[qi];
                s += q[qi*4+0]*b.x + q[qi*4+1]*b.y + q[qi*4+2]*b.z + q[qi*4+3]*b.w;
            }
            s += __shfl_xor_sync(0xffffffffu, s, 1);
            s += __shfl_xor_sync(0xffffffffu, s, 2);
            s += bcoef;
            if (s > m) {
                float al = __expf(m - s);
                l *= al;
#pragma unroll
                for (int k = 0; k < 16; ++k) racc[k] *= al;
                m = s;
            }
            float p = __expf(s - m);
            l += p;
            const float4* yv = (const float4*)&ya[jt][x4*16];
#pragma unroll
            for (int k4 = 0; k4 < 4; ++k4) {
                float4 b = yv[k4];
                racc[k4*4+0] += p*b.x; racc[k4*4+1] += p*b.y;
                racc[k4*4+2] += p*b.z; racc[k4*4+3] += p*b.w;
            }
        }
    }

    const float invl = 1.f / l;
    float* outp = &g_ret[((size_t)seg*LL + tq)*64 + x4*16];
#pragma unroll
    for (int k4 = 0; k4 < 4; ++k4) {
        float4 v;
        v.x = racc[k4*4+0]*invl; v.y = racc[k4*4+1]*invl;
        v.z = racc[k4*4+2]*invl; v.w = racc[k4*4+3]*invl;
        ((float4*)outp)[k4] = v;
    }
    if (x4 == 0) g_bsc[seg*LL + tq] = m + __logf(l);
}

// =======================================================================
// K6: per-token softmax over heads + residual, NCHW output
// =======================================================================
__global__ __launch_bounds__(256) void final_kernel(
    const float* __restrict__ x, float* __restrict__ out)
{
    const int tg = blockIdx.x*256 + threadIdx.x;  // < 18432
    const int n = tg / LL, tt = tg % LL;
    float b[4];
    float mx = -1e30f;
#pragma unroll
    for (int h = 0; h < 4; ++h) {
        b[h] = g_bsc[(n*4+h)*LL + tt];
        mx = fmaxf(mx, b[h]);
    }
    float wsum = 0.f;
#pragma unroll
    for (int h = 0; h < 4; ++h) { b[h] = __expf(b[h] - mx); wsum += b[h]; }
    const float inv = 1.f / wsum;
#pragma unroll
    for (int c4 = 0; c4 < 16; ++c4) {
        float4 acc = {0.f, 0.f, 0.f, 0.f};
#pragma unroll
        for (int h = 0; h < 4; ++h) {
            float4 r = *(const float4*)&g_ret[((size_t)(n*4+h)*LL + tt)*64 + c4*4];
            float wv = b[h]*inv;
            acc.x += wv*r.x; acc.y += wv*r.y; acc.z += wv*r.z; acc.w += wv*r.w;
        }
        int c = c4*4;
        out[(n*64+c  )*LL + tt] = acc.x + x[(n*64+c  )*LL + tt];
        out[(n*64+c+1)*LL + tt] = acc.y + x[(n*64+c+1)*LL + tt];
        out[(n*64+c+2)*LL + tt] = acc.z + x[(n*64+c+2)*LL + tt];
        out[(n*64+c+3)*LL + tt] = acc.w + x[(n*64+c+3)*LL + tt];
    }
}

// =======================================================================
extern "C" void kernel_launch(void* const* d_in, const int* in_sizes, int n_in,
                              void* d_out, int out_size)
{
    const float* x     = (const float*)d_in[0];
    const float* rot   = (const float*)d_in[1];
    const float* wm    = (const float*)d_in[2];
    const float* bm    = (const float*)d_in[3];
    const float* wa    = (const float*)d_in[4];
    const float* ba    = (const float*)d_in[5];
    const float* wf    = (const float*)d_in[6];
    const float* bf    = (const float*)d_in[7];
    const float* fc1_w = (const float*)d_in[8];
    const float* fc1_b = (const float*)d_in[9];
    const float* fc2_w = (const float*)d_in[10];
    const float* fc2_b = (const float*)d_in[11];
    float* out = (float*)d_out;

    conv_kernel <<<dim3(96, 2, 2), dim3(96, 3)>>>(x, wm, bm, wa, ba, wf, bf);
    code_kernel <<<72, 256>>>(rot);
    sort_kernel <<<8, 256>>>();
    hid_kernel  <<<1152, 256>>>(fc1_w, fc1_b);
    attn_kernel <<<dim3(64, 4, 2), dim3(4, 144)>>>(fc2_w, fc2_b);
    final_kernel<<<72, 256>>>(x, out);
}

// round 7
// speedup vs baseline: 1.0502x; 1.0502x over previous
#include <cuda_runtime.h>
#include <math.h>

#define NB 2
#define LL 9216
#define NHH 4
#define CHK 144
#define NCHK 64
#define TOKS (NB*LL)

// ---------------- static scratch ----------------
__device__ float g_xe[TOKS*16];
__device__ float g_xm[TOKS*16];
__device__ float g_ye[(size_t)TOKS*64];
__device__ float g_fe[(size_t)TOKS*64];
__device__ float g_H [(size_t)TOKS*144];
__device__ unsigned char g_code[NB*NHH*LL];
__device__ int   g_perm[NB*NHH*LL];
__device__ float g_bsc[NB*NHH*LL];
__device__ float g_ret[(size_t)NB*NHH*LL*64];

// ---------------- packed f32x2 helpers ----------------
__device__ __forceinline__ unsigned long long pk2(float a, float b) {
    unsigned long long r;
    asm("mov.b64 %0,{%1,%2};" : "=l"(r) : "f"(a), "f"(b));
    return r;
}
__device__ __forceinline__ void upk2(unsigned long long v, float& a, float& b) {
    asm("mov.b64 {%0,%1},%2;" : "=f"(a), "=f"(b) : "l"(v));
}
__device__ __forceinline__ unsigned long long fma2(unsigned long long a,
                                                   unsigned long long b,
                                                   unsigned long long c) {
    unsigned long long d;
    asm("fma.rn.f32x2 %0,%1,%2,%3;" : "=l"(d) : "l"(a), "l"(b), "l"(c));
    return d;
}
__device__ __forceinline__ unsigned long long mul2_(unsigned long long a,
                                                    unsigned long long b) {
    unsigned long long d;
    asm("mul.rn.f32x2 %0,%1,%2;" : "=l"(d) : "l"(a), "l"(b));
    return d;
}
__device__ __forceinline__ float ex2f(float x) {
    float y; asm("ex2.approx.ftz.f32 %0,%1;" : "=f"(y) : "f"(x)); return y;
}
__device__ __forceinline__ float lg2f(float x) {
    float y; asm("lg2.approx.ftz.f32 %0,%1;" : "=f"(y) : "f"(x)); return y;
}
#define LOG2E 1.4426950408889634f
#define LN2   0.6931471805599453f

// =======================================================================
// K1: fused 3x3 SAME conv (144 out ch) + ReLU -> xe(16), ye(64), fe(64)
// grid (96=y, 2=n, 2=co-half), block (96, 3). Packed f32x2 over co pairs.
// =======================================================================
__global__ __launch_bounds__(288) void conv_kernel(
    const float* __restrict__ x,
    const float* __restrict__ wm, const float* __restrict__ bm,
    const float* __restrict__ wa, const float* __restrict__ ba,
    const float* __restrict__ wf, const float* __restrict__ bf)
{
    __shared__ float in_sh[8][3][100];
    __shared__ __align__(16) float w_sh[8][9][72];   // [ci][tap][co]

    const int y    = blockIdx.x;
    const int n    = blockIdx.y;
    const int half = blockIdx.z;
    const int xcol = threadIdx.x;          // 0..95
    const int lane = threadIdx.y;          // 0..2
    const int tid  = xcol + 96*lane;       // 0..287
    const int coBase = half*72;

    unsigned long long acc2[12];
#pragma unroll
    for (int m = 0; m < 12; ++m) acc2[m] = 0ull;

    for (int cb = 0; cb < 8; ++cb) {
        __syncthreads();
        for (int idx = tid; idx < 8*3*98; idx += 288) {
            int c = idx / 294, rem = idx % 294, r = rem / 98, xx = rem % 98;
            int gy = y - 1 + r, gx = xx - 1, ci = cb*8 + c;
            float v = 0.f;
            if (gy >= 0 && gy < 96 && gx >= 0 && gx < 96)
                v = x[((n*64 + ci)*96 + gy)*96 + gx];
            in_sh[c][r][xx] = v;
        }
        for (int idx = tid; idx < 8*72*9; idx += 288) {
            int c = idx / 648, rem = idx % 648, tap = rem / 72, co_l = rem % 72;
            int co = coBase + co_l, ci = cb*8 + c;
            float w;
            if (co < 16)      w = wm[( co      *64 + ci)*9 + tap];
            else if (co < 80) w = wa[((co-16)*64 + ci)*9 + tap];
            else              w = wf[((co-80)*64 + ci)*9 + tap];
            w_sh[c][tap][co_l] = w;
        }
        __syncthreads();
#pragma unroll
        for (int c = 0; c < 8; ++c) {
            unsigned long long d[9];
            d[0] = pk2(in_sh[c][0][xcol],   in_sh[c][0][xcol]);
            d[1] = pk2(in_sh[c][0][xcol+1], in_sh[c][0][xcol+1]);
            d[2] = pk2(in_sh[c][0][xcol+2], in_sh[c][0][xcol+2]);
            d[3] = pk2(in_sh[c][1][xcol],   in_sh[c][1][xcol]);
            d[4] = pk2(in_sh[c][1][xcol+1], in_sh[c][1][xcol+1]);
            d[5] = pk2(in_sh[c][1][xcol+2], in_sh[c][1][xcol+2]);
            d[6] = pk2(in_sh[c][2][xcol],   in_sh[c][2][xcol]);
            d[7] = pk2(in_sh[c][2][xcol+1], in_sh[c][2][xcol+1]);
            d[8] = pk2(in_sh[c][2][xcol+2], in_sh[c][2][xcol+2]);
#pragma unroll
            for (int tap = 0; tap < 9; ++tap) {
                const ulonglong2* wp = (const ulonglong2*)&w_sh[c][tap][lane*24];
#pragma unroll
                for (int v = 0; v < 6; ++v) {
                    ulonglong2 w4 = wp[v];
                    acc2[2*v]   = fma2(d[tap], w4.x, acc2[2*v]);
                    acc2[2*v+1] = fma2(d[tap], w4.y, acc2[2*v+1]);
                }
            }
        }
    }

    const int tok = n*LL + y*96 + xcol;
    float acc[24];
#pragma unroll
    for (int m = 0; m < 12; ++m) upk2(acc2[m], acc[2*m], acc[2*m+1]);
#pragma unroll
    for (int m = 0; m < 24; ++m) {
        int co = coBase + lane*24 + m;
        if (co < 16) {
            g_xe[tok*16 + co] = fmaxf(acc[m] + bm[co], 0.f);
        } else if (co < 80) {
            g_ye[(size_t)tok*64 + (co-16)] = fmaxf(acc[m] + ba[co-16], 0.f);
        } else {
            g_fe[(size_t)tok*64 + (co-80)] = fmaxf(acc[m] + bf[co-80], 0.f);
        }
    }
}

// =======================================================================
// K2: LSH codes (argmax over 64 rotated dirs per head) + normalized xm
// =======================================================================
__global__ __launch_bounds__(256) void code_kernel(const float* __restrict__ rot)
{
    __shared__ __align__(16) float rotT[4096];   // [(h*64+i)*16 + f]
    const int tid = threadIdx.x;
    for (int idx = tid; idx < 4096; idx += 256) {
        int hi = idx >> 4, f = idx & 15;
        rotT[idx] = rot[f*256 + hi];     // rot (16, 4, 64)
    }
    __syncthreads();

    const int tg = blockIdx.x*256 + tid;
    const int n = tg / LL, t = tg % LL;

    const ulonglong2* ep = (const ulonglong2*)&g_xe[tg*16];
    unsigned long long ev[8];
#pragma unroll
    for (int i = 0; i < 4; ++i) { ulonglong2 v = ep[i]; ev[2*i] = v.x; ev[2*i+1] = v.y; }

    unsigned long long ssp = 0ull;
#pragma unroll
    for (int i = 0; i < 8; ++i) ssp = fma2(ev[i], ev[i], ssp);
    float slo, shi; upk2(ssp, slo, shi);
    float inv = 1.f / fmaxf(sqrtf(slo + shi), 5e-5f);
    unsigned long long invd = pk2(inv, inv);
    ulonglong2* xmp = (ulonglong2*)&g_xm[tg*16];
#pragma unroll
    for (int i = 0; i < 4; ++i) {
        ulonglong2 o;
        o.x = mul2_(ev[2*i], invd); o.y = mul2_(ev[2*i+1], invd);
        xmp[i] = o;
    }

#pragma unroll
    for (int h = 0; h < 4; ++h) {
        float best = -1e30f; int bi = 0;
        for (int i = 0; i < 64; ++i) {
            const unsigned long long* rr = (const unsigned long long*)&rotT[(h*64+i)*16];
            unsigned long long sp = 0ull;
#pragma unroll
            for (int j = 0; j < 8; ++j) sp = fma2(ev[j], rr[j], sp);
            float a, b; upk2(sp, a, b);
            float dd = a + b;
            if (dd > best) { best = dd; bi = i; }
        }
        g_code[(n*4+h)*LL + t] = (unsigned char)bi;
    }
}

// =======================================================================
// K3: per-(n,h) stable counting sort over 64 buckets -> g_perm
// =======================================================================
__global__ __launch_bounds__(256) void sort_kernel()
{
    const int seg = blockIdx.x;            // 0..7
    __shared__ int hist[64];
    __shared__ int running[64];
    __shared__ int wh[8][64];
    const int tid = threadIdx.x;
    const int w = tid >> 5, ln = tid & 31;

    if (tid < 64) hist[tid] = 0;
    __syncthreads();
    const unsigned char* code = &g_code[seg*LL];
    for (int t = tid; t < LL; t += 256) atomicAdd(&hist[code[t]], 1);
    __syncthreads();
    if (tid == 0) {
        int acc = 0;
        for (int b = 0; b < 64; ++b) { running[b] = acc; acc += hist[b]; }
    }
    __syncthreads();

    for (int tile = 0; tile < 36; ++tile) {
        int t = tile*256 + tid;
        int c = code[t];
        unsigned mask = __match_any_sync(0xffffffffu, c);
        int lanerank = __popc(mask & ((1u << ln) - 1u));
        ((int*)wh)[tid] = 0; ((int*)wh)[tid + 256] = 0;
        __syncthreads();
        if (lanerank == 0) wh[w][c] = __popc(mask);
        __syncthreads();
        int r = lanerank;
        for (int w2 = 0; w2 < w; ++w2) r += wh[w2][c];
        int pos = running[c] + r;
        __syncthreads();
        if (tid < 64) {
            int s = 0;
            for (int w2 = 0; w2 < 8; ++w2) s += wh[w2][tid];
            running[tid] += s;
        }
        __syncthreads();
        g_perm[seg*LL + pos] = t;
    }
}

// =======================================================================
// K4: H = relu(fe @ fc1_w^T + fc1_b). Register-tiled: 32 tok x 144 col / block,
// thread = 2 tok x 18 cols, k-packed f32x2 accumulation.
// =======================================================================
__global__ __launch_bounds__(256) void hid_kernel(
    const float* __restrict__ fc1_w, const float* __restrict__ fc1_b)
{
    __shared__ __align__(16) float w_sh[144][68];   // [col][k]
    __shared__ __align__(16) float fe_sh[32][68];   // [tok][k]
    __shared__ float b_sh[144];

    const int tid = threadIdx.x;
    for (int idx = tid; idx < 144*16; idx += 256) {
        int col = idx >> 4, kq = idx & 15;
        *(float4*)&w_sh[col][kq*4] = *(const float4*)&fc1_w[col*64 + kq*4];
    }
    if (tid < 144) b_sh[tid] = fc1_b[tid];
    const int tok0 = blockIdx.x * 32;
    for (int idx = tid; idx < 32*16; idx += 256) {
        int t = idx >> 4, kq = idx & 15;
        *(float4*)&fe_sh[t][kq*4] = *(const float4*)&g_fe[(size_t)(tok0+t)*64 + kq*4];
    }
    __syncthreads();

    const int cg = tid & 15;     // 16 col groups of 9
    const int tg = tid >> 4;     // 16 tok groups of 2
    const int c0 = cg * 9;
    const int t0 = tg * 2;

    unsigned long long acc[18];
#pragma unroll
    for (int j = 0; j < 18; ++j) acc[j] = 0ull;

#pragma unroll
    for (int kk = 0; kk < 16; ++kk) {
        ulonglong2 f0 = *(const ulonglong2*)&fe_sh[t0][kk*4];
        ulonglong2 f1 = *(const ulonglong2*)&fe_sh[t0+1][kk*4];
#pragma unroll
        for (int j = 0; j < 9; ++j) {
            ulonglong2 w4 = *(const ulonglong2*)&w_sh[c0+j][kk*4];
            acc[j]   = fma2(f0.x, w4.x, acc[j]);
            acc[j]   = fma2(f0.y, w4.y, acc[j]);
            acc[9+j] = fma2(f1.x, w4.x, acc[9+j]);
            acc[9+j] = fma2(f1.y, w4.y, acc[9+j]);
        }
    }
#pragma unroll
    for (int t = 0; t < 2; ++t)
#pragma unroll
        for (int j = 0; j < 9; ++j) {
            float lo, hi; upk2(acc[t*9+j], lo, hi);
            float s = lo + hi + b_sh[c0+j];
            g_H[(size_t)(tok0 + t0 + t)*144 + c0 + j] = fmaxf(s, 0.f);
        }
}

// =======================================================================
// K5: fused flash attention per (n,h,chunk). 432 keys = chunks {c,c-1,c+1}.
// logits = xs·xmatch + fc2_w[i]·H_j + fc2_b[i] (base-2 domain).
// block (4,144): e-dim split 4x, f32x2-packed dot + accumulation.
// =======================================================================
__global__ __launch_bounds__(576, 1) void attn_kernel(
    const float* __restrict__ fc2_w, const float* __restrict__ fc2_b)
{
    __shared__ __align__(16) float kf[48][160];   // [key][xm(16) | H(144)]
    __shared__ __align__(16) float ya[48][64];

    const int cblk = blockIdx.x;
    const int h    = blockIdx.y;
    const int n    = blockIdx.z;
    const int seg  = n*4 + h;
    const int x4   = threadIdx.x;           // 0..3 (e-quarter)
    const int i    = threadIdx.y;           // 0..143 (query)
    const int tid  = x4 + 4*i;

    const int tq  = g_perm[seg*LL + cblk*CHK + i];
    const int tqg = n*LL + tq;

    unsigned long long q2[20];
#pragma unroll
    for (int e2 = 0; e2 < 20; ++e2) {
        int f0 = x4*40 + e2*2;
        float a, b;
        if (f0 < 16) { a = g_xe[tqg*16 + f0];        b = g_xe[tqg*16 + f0 + 1]; }
        else         { a = fc2_w[i*144 + (f0-16)];   b = fc2_w[i*144 + (f0-15)]; }
        q2[e2] = pk2(a*LOG2E, b*LOG2E);
    }
    const float bcoef = fc2_b[i]*LOG2E;

    float m = -1e30f, l = 0.f;
    unsigned long long racc[8];
#pragma unroll
    for (int k = 0; k < 8; ++k) racc[k] = 0ull;

    for (int tilej = 0; tilej < 9; ++tilej) {
        const int j0 = tilej * 48;
        __syncthreads();
        for (int idx = tid; idx < 48*56; idx += 576) {
            int jj = idx / 56, comp = idx % 56;
            int j = j0 + jj;
            int jb = j / 144, jr = j % 144;
            int cc = cblk + (jb == 1 ? -1 : (jb == 2 ? 1 : 0));
            cc = (cc + 64) & 63;
            int tk  = g_perm[seg*LL + cc*CHK + jr];
            int tkg = n*LL + tk;
            float4 v;
            if (comp < 4)       v = *(const float4*)&g_xm[tkg*16 + comp*4];
            else if (comp < 40) v = *(const float4*)&g_H[(size_t)tkg*144 + (comp-4)*4];
            else                v = *(const float4*)&g_ye[(size_t)tkg*64 + (comp-40)*4];
            if (comp < 40) *(float4*)&kf[jj][comp*4] = v;
            else           *(float4*)&ya[jj][(comp-40)*4] = v;
        }
        __syncthreads();

#pragma unroll 2
        for (int jt = 0; jt < 48; ++jt) {
            const ulonglong2* kv = (const ulonglong2*)&kf[jt][x4*40];
            unsigned long long sp = 0ull;
#pragma unroll
            for (int qi = 0; qi < 10; ++qi) {
                ulonglong2 b = kv[qi];
                sp = fma2(q2[2*qi],   b.x, sp);
                sp = fma2(q2[2*qi+1], b.y, sp);
            }
            float slo, shi; upk2(sp, slo, shi);
            float s = slo + shi;
            s += __shfl_xor_sync(0xffffffffu, s, 1);
            s += __shfl_xor_sync(0xffffffffu, s, 2);
            s += bcoef;
            if (s > m) {
                float al = ex2f(m - s);
                unsigned long long al2 = pk2(al, al);
                l *= al;
#pragma unroll
                for (int k = 0; k < 8; ++k) racc[k] = mul2_(racc[k], al2);
                m = s;
            }
            float p = ex2f(s - m);
            l += p;
            unsigned long long p2 = pk2(p, p);
            const ulonglong2* yv = (const ulonglong2*)&ya[jt][x4*16];
#pragma unroll
            for (int k4 = 0; k4 < 4; ++k4) {
                ulonglong2 b = yv[k4];
                racc[k4*2]   = fma2(p2, b.x, racc[k4*2]);
                racc[k4*2+1] = fma2(p2, b.y, racc[k4*2+1]);
            }
        }
    }

    const float invl = 1.f / l;
    unsigned long long invd = pk2(invl, invl);
    float* outp = &g_ret[((size_t)seg*LL + tq)*64 + x4*16];
#pragma unroll
    for (int k4 = 0; k4 < 4; ++k4) {
        ulonglong2 o;
        o.x = mul2_(racc[k4*2],   invd);
        o.y = mul2_(racc[k4*2+1], invd);
        *(ulonglong2*)&outp[k4*4] = o;
    }
    if (x4 == 0) g_bsc[seg*LL + tq] = (m + lg2f(l)) * LN2;
}

// =======================================================================
// K6: per-token softmax over heads + residual, NCHW output
// =======================================================================
__global__ __launch_bounds__(256) void final_kernel(
    const float* __restrict__ x, float* __restrict__ out)
{
    const int tg = blockIdx.x*256 + threadIdx.x;
    const int n = tg / LL, tt = tg % LL;
    float b[4];
    float mx = -1e30f;
#pragma unroll
    for (int h = 0; h < 4; ++h) {
        b[h] = g_bsc[(n*4+h)*LL + tt];
        mx = fmaxf(mx, b[h]);
    }
    float wsum = 0.f;
#pragma unroll
    for (int h = 0; h < 4; ++h) { b[h] = __expf(b[h] - mx); wsum += b[h]; }
    const float inv = 1.f / wsum;
#pragma unroll
    for (int c4 = 0; c4 < 16; ++c4) {
        float4 acc = {0.f, 0.f, 0.f, 0.f};
#pragma unroll
        for (int h = 0; h < 4; ++h) {
            float4 r = *(const float4*)&g_ret[((size_t)(n*4+h)*LL + tt)*64 + c4*4];
            float wv = b[h]*inv;
            acc.x += wv*r.x; acc.y += wv*r.y; acc.z += wv*r.z; acc.w += wv*r.w;
        }
        int c = c4*4;
        out[(n*64+c  )*LL + tt] = acc.x + x[(n*64+c  )*LL + tt];
        out[(n*64+c+1)*LL + tt] = acc.y + x[(n*64+c+1)*LL + tt];
        out[(n*64+c+2)*LL + tt] = acc.z + x[(n*64+c+2)*LL + tt];
        out[(n*64+c+3)*LL + tt] = acc.w + x[(n*64+c+3)*LL + tt];
    }
}

// =======================================================================
extern "C" void kernel_launch(void* const* d_in, const int* in_sizes, int n_in,
                              void* d_out, int out_size)
{
    const float* x     = (const float*)d_in[0];
    const float* rot   = (const float*)d_in[1];
    const float* wm    = (const float*)d_in[2];
    const float* bm    = (const float*)d_in[3];
    const float* wa    = (const float*)d_in[4];
    const float* ba    = (const float*)d_in[5];
    const float* wf    = (const float*)d_in[6];
    const float* bf    = (const float*)d_in[7];
    const float* fc1_w = (const float*)d_in[8];
    const float* fc1_b = (const float*)d_in[9];
    const float* fc2_w = (const float*)d_in[10];
    const float* fc2_b = (const float*)d_in[11];
    float* out = (float*)d_out;

    conv_kernel <<<dim3(96, 2, 2), dim3(96, 3)>>>(x, wm, bm, wa, ba, wf, bf);
    code_kernel <<<72, 256>>>(rot);
    sort_kernel <<<8, 256>>>();
    hid_kernel  <<<576, 256>>>(fc1_w, fc1_b);
    attn_kernel <<<dim3(64, 4, 2), dim3(4, 144)>>>(fc2_w, fc2_b);
    final_kernel<<<72, 256>>>(x, out);
}

// round 10
// speedup vs baseline: 1.9177x; 1.8260x over previous
#include <cuda_runtime.h>
#include <math.h>

#define NB 2
#define LL 9216
#define NHH 4
#define CHK 144
#define NCHK 64
#define TOKS (NB*LL)

// ---------------- static scratch ----------------
__device__ float g_xe[TOKS*16];
__device__ float g_xm[TOKS*16];
__device__ float g_ye[(size_t)TOKS*64];
__device__ float g_fe[(size_t)TOKS*64];
__device__ float g_H [(size_t)TOKS*144];
__device__ unsigned char g_code[NB*NHH*LL];
__device__ int   g_perm[NB*NHH*LL];
__device__ float g_bsc[NB*NHH*LL];
__device__ float g_ret[(size_t)NB*NHH*LL*64];
// pre-gathered per-(seg,chunk) K rows ([xm|H]*LOG2E) and Y rows
__device__ float g_K[(size_t)8*64*144*160];
__device__ float g_Y[(size_t)8*64*144*64];

// ---------------- packed f32x2 helpers ----------------
typedef unsigned long long ull;
__device__ __forceinline__ ull pk2(float a, float b) {
    ull r; asm("mov.b64 %0,{%1,%2};" : "=l"(r) : "f"(a), "f"(b)); return r;
}
__device__ __forceinline__ void upk2(ull v, float& a, float& b) {
    asm("mov.b64 {%0,%1},%2;" : "=f"(a), "=f"(b) : "l"(v));
}
__device__ __forceinline__ ull fma2(ull a, ull b, ull c) {
    ull d; asm("fma.rn.f32x2 %0,%1,%2,%3;" : "=l"(d) : "l"(a), "l"(b), "l"(c)); return d;
}
__device__ __forceinline__ ull mul2_(ull a, ull b) {
    ull d; asm("mul.rn.f32x2 %0,%1,%2;" : "=l"(d) : "l"(a), "l"(b)); return d;
}
__device__ __forceinline__ float ex2f(float x) {
    float y; asm("ex2.approx.ftz.f32 %0,%1;" : "=f"(y) : "f"(x)); return y;
}
__device__ __forceinline__ float lg2f(float x) {
    float y; asm("lg2.approx.ftz.f32 %0,%1;" : "=f"(y) : "f"(x)); return y;
}
#define LOG2E 1.4426950408889634f
#define LN2   0.6931471805599453f

// =======================================================================
// K1: fused 3x3 SAME conv (144 out ch) + ReLU -> xe(16), ye(64), fe(64)
// grid (96=y, 2=n, 2=co-half), block (96, 3)
// =======================================================================
__global__ __launch_bounds__(288) void conv_kernel(
    const float* __restrict__ x,
    const float* __restrict__ wm, const float* __restrict__ bm,
    const float* __restrict__ wa, const float* __restrict__ ba,
    const float* __restrict__ wf, const float* __restrict__ bf)
{
    __shared__ float in_sh[8][3][100];
    __shared__ __align__(16) float w_sh[8][9][72];

    const int y    = blockIdx.x;
    const int n    = blockIdx.y;
    const int half = blockIdx.z;
    const int xcol = threadIdx.x;
    const int lane = threadIdx.y;
    const int tid  = xcol + 96*lane;
    const int coBase = half*72;

    ull acc2[12];
#pragma unroll
    for (int m = 0; m < 12; ++m) acc2[m] = 0ull;

    for (int cb = 0; cb < 8; ++cb) {
        __syncthreads();
        for (int idx = tid; idx < 8*3*98; idx += 288) {
            int c = idx / 294, rem = idx % 294, r = rem / 98, xx = rem % 98;
            int gy = y - 1 + r, gx = xx - 1, ci = cb*8 + c;
            float v = 0.f;
            if (gy >= 0 && gy < 96 && gx >= 0 && gx < 96)
                v = x[((n*64 + ci)*96 + gy)*96 + gx];
            in_sh[c][r][xx] = v;
        }
        for (int idx = tid; idx < 8*72*9; idx += 288) {
            int c = idx / 648, rem = idx % 648, tap = rem / 72, co_l = rem % 72;
            int co = coBase + co_l, ci = cb*8 + c;
            float w;
            if (co < 16)      w = wm[( co      *64 + ci)*9 + tap];
            else if (co < 80) w = wa[((co-16)*64 + ci)*9 + tap];
            else              w = wf[((co-80)*64 + ci)*9 + tap];
            w_sh[c][tap][co_l] = w;
        }
        __syncthreads();
#pragma unroll
        for (int c = 0; c < 8; ++c) {
            ull d[9];
            d[0] = pk2(in_sh[c][0][xcol],   in_sh[c][0][xcol]);
            d[1] = pk2(in_sh[c][0][xcol+1], in_sh[c][0][xcol+1]);
            d[2] = pk2(in_sh[c][0][xcol+2], in_sh[c][0][xcol+2]);
            d[3] = pk2(in_sh[c][1][xcol],   in_sh[c][1][xcol]);
            d[4] = pk2(in_sh[c][1][xcol+1], in_sh[c][1][xcol+1]);
            d[5] = pk2(in_sh[c][1][xcol+2], in_sh[c][1][xcol+2]);
            d[6] = pk2(in_sh[c][2][xcol],   in_sh[c][2][xcol]);
            d[7] = pk2(in_sh[c][2][xcol+1], in_sh[c][2][xcol+1]);
            d[8] = pk2(in_sh[c][2][xcol+2], in_sh[c][2][xcol+2]);
#pragma unroll
            for (int tap = 0; tap < 9; ++tap) {
                const ulonglong2* wp = (const ulonglong2*)&w_sh[c][tap][lane*24];
#pragma unroll
                for (int v = 0; v < 6; ++v) {
                    ulonglong2 w4 = wp[v];
                    acc2[2*v]   = fma2(d[tap], w4.x, acc2[2*v]);
                    acc2[2*v+1] = fma2(d[tap], w4.y, acc2[2*v+1]);
                }
            }
        }
    }

    const int tok = n*LL + y*96 + xcol;
    float acc[24];
#pragma unroll
    for (int m = 0; m < 12; ++m) upk2(acc2[m], acc[2*m], acc[2*m+1]);
#pragma unroll
    for (int m = 0; m < 24; ++m) {
        int co = coBase + lane*24 + m;
        if (co < 16) {
            g_xe[tok*16 + co] = fmaxf(acc[m] + bm[co], 0.f);
        } else if (co < 80) {
            g_ye[(size_t)tok*64 + (co-16)] = fmaxf(acc[m] + ba[co-16], 0.f);
        } else {
            g_fe[(size_t)tok*64 + (co-80)] = fmaxf(acc[m] + bf[co-80], 0.f);
        }
    }
}

// =======================================================================
// K2: LSH codes (argmax over 64 rotated dirs per head) + normalized xm
// =======================================================================
__global__ __launch_bounds__(256) void code_kernel(const float* __restrict__ rot)
{
    __shared__ __align__(16) float rotT[4096];
    const int tid = threadIdx.x;
    for (int idx = tid; idx < 4096; idx += 256) {
        int hi = idx >> 4, f = idx & 15;
        rotT[idx] = rot[f*256 + hi];
    }
    __syncthreads();

    const int tg = blockIdx.x*256 + tid;
    const int n = tg / LL, t = tg % LL;

    const ulonglong2* ep = (const ulonglong2*)&g_xe[tg*16];
    ull ev[8];
#pragma unroll
    for (int i = 0; i < 4; ++i) { ulonglong2 v = ep[i]; ev[2*i] = v.x; ev[2*i+1] = v.y; }

    ull ssp = 0ull;
#pragma unroll
    for (int i = 0; i < 8; ++i) ssp = fma2(ev[i], ev[i], ssp);
    float slo, shi; upk2(ssp, slo, shi);
    float inv = 1.f / fmaxf(sqrtf(slo + shi), 5e-5f);
    ull invd = pk2(inv, inv);
    ulonglong2* xmp = (ulonglong2*)&g_xm[tg*16];
#pragma unroll
    for (int i = 0; i < 4; ++i) {
        ulonglong2 o;
        o.x = mul2_(ev[2*i], invd); o.y = mul2_(ev[2*i+1], invd);
        xmp[i] = o;
    }

#pragma unroll
    for (int h = 0; h < 4; ++h) {
        float best = -1e30f; int bi = 0;
        for (int i = 0; i < 64; ++i) {
            const ull* rr = (const ull*)&rotT[(h*64+i)*16];
            ull sp = 0ull;
#pragma unroll
            for (int j = 0; j < 8; ++j) sp = fma2(ev[j], rr[j], sp);
            float a, b; upk2(sp, a, b);
            float dd = a + b;
            if (dd > best) { best = dd; bi = i; }
        }
        g_code[(n*4+h)*LL + t] = (unsigned char)bi;
    }
}

// =======================================================================
// K3: per-(n,h) stable counting sort over 64 buckets -> g_perm
// =======================================================================
__global__ __launch_bounds__(256) void sort_kernel()
{
    const int seg = blockIdx.x;
    __shared__ int hist[64];
    __shared__ int running[64];
    __shared__ int wh[8][64];
    const int tid = threadIdx.x;
    const int w = tid >> 5, ln = tid & 31;

    if (tid < 64) hist[tid] = 0;
    __syncthreads();
    const unsigned char* code = &g_code[seg*LL];
    for (int t = tid; t < LL; t += 256) atomicAdd(&hist[code[t]], 1);
    __syncthreads();
    if (tid == 0) {
        int acc = 0;
        for (int b = 0; b < 64; ++b) { running[b] = acc; acc += hist[b]; }
    }
    __syncthreads();

    for (int tile = 0; tile < 36; ++tile) {
        int t = tile*256 + tid;
        int c = code[t];
        unsigned mask = __match_any_sync(0xffffffffu, c);
        int lanerank = __popc(mask & ((1u << ln) - 1u));
        ((int*)wh)[tid] = 0; ((int*)wh)[tid + 256] = 0;
        __syncthreads();
        if (lanerank == 0) wh[w][c] = __popc(mask);
        __syncthreads();
        int r = lanerank;
        for (int w2 = 0; w2 < w; ++w2) r += wh[w2][c];
        int pos = running[c] + r;
        __syncthreads();
        if (tid < 64) {
            int s = 0;
            for (int w2 = 0; w2 < 8; ++w2) s += wh[w2][tid];
            running[tid] += s;
        }
        __syncthreads();
        g_perm[seg*LL + pos] = t;
    }
}

// =======================================================================
// K4: H = relu(fe @ fc1_w^T + fc1_b)
// =======================================================================
__global__ __launch_bounds__(256) void hid_kernel(
    const float* __restrict__ fc1_w, const float* __restrict__ fc1_b)
{
    __shared__ __align__(16) float w_sh[144][68];
    __shared__ __align__(16) float fe_sh[32][68];
    __shared__ float b_sh[144];

    const int tid = threadIdx.x;
    for (int idx = tid; idx < 144*16; idx += 256) {
        int col = idx >> 4, kq = idx & 15;
        *(float4*)&w_sh[col][kq*4] = *(const float4*)&fc1_w[col*64 + kq*4];
    }
    if (tid < 144) b_sh[tid] = fc1_b[tid];
    const int tok0 = blockIdx.x * 32;
    for (int idx = tid; idx < 32*16; idx += 256) {
        int t = idx >> 4, kq = idx & 15;
        *(float4*)&fe_sh[t][kq*4] = *(const float4*)&g_fe[(size_t)(tok0+t)*64 + kq*4];
    }
    __syncthreads();

    const int cg = tid & 15;
    const int tg = tid >> 4;
    const int c0 = cg * 9;
    const int t0 = tg * 2;

    ull acc[18];
#pragma unroll
    for (int j = 0; j < 18; ++j) acc[j] = 0ull;

#pragma unroll
    for (int kk = 0; kk < 16; ++kk) {
        ulonglong2 f0 = *(const ulonglong2*)&fe_sh[t0][kk*4];
        ulonglong2 f1 = *(const ulonglong2*)&fe_sh[t0+1][kk*4];
#pragma unroll
        for (int j = 0; j < 9; ++j) {
            ulonglong2 w4 = *(const ulonglong2*)&w_sh[c0+j][kk*4];
            acc[j]   = fma2(f0.x, w4.x, acc[j]);
            acc[j]   = fma2(f0.y, w4.y, acc[j]);
            acc[9+j] = fma2(f1.x, w4.x, acc[9+j]);
            acc[9+j] = fma2(f1.y, w4.y, acc[9+j]);
        }
    }
#pragma unroll
    for (int t = 0; t < 2; ++t)
#pragma unroll
        for (int j = 0; j < 9; ++j) {
            float lo, hi; upk2(acc[t*9+j], lo, hi);
            float s = lo + hi + b_sh[c0+j];
            g_H[(size_t)(tok0 + t0 + t)*144 + c0 + j] = fmaxf(s, 0.f);
        }
}

// =======================================================================
// K4b: prep — gather per-(seg,chunk) K rows ([xm|H]*LOG2E) and Y rows (ye)
// =======================================================================
__global__ __launch_bounds__(256) void prep_kernel()
{
    const int chunk = blockIdx.x;
    const int seg   = blockIdx.y;
    const int n     = seg >> 2;
    const int tid   = threadIdx.x;

    __shared__ int tq_sh[144];
    if (tid < 144) tq_sh[tid] = g_perm[seg*LL + chunk*CHK + tid];
    __syncthreads();

    float* Kdst = &g_K[((size_t)(seg*64 + chunk))*144*160];
    for (int idx = tid; idx < 144*40; idx += 256) {
        int i = idx / 40, d4 = idx % 40;
        int tokg = n*LL + tq_sh[i];
        float4 v;
        if (d4 < 4) v = *(const float4*)&g_xm[tokg*16 + d4*4];
        else        v = *(const float4*)&g_H[(size_t)tokg*144 + (d4-4)*4];
        v.x *= LOG2E; v.y *= LOG2E; v.z *= LOG2E; v.w *= LOG2E;
        *(float4*)&Kdst[i*160 + d4*4] = v;
    }
    float* Ydst = &g_Y[((size_t)(seg*64 + chunk))*144*64];
    for (int idx = tid; idx < 144*16; idx += 256) {
        int i = idx / 16, e4 = idx % 16;
        int tokg = n*LL + tq_sh[i];
        *(float4*)&Ydst[i*64 + e4*4] = *(const float4*)&g_ye[(size_t)tokg*64 + e4*4];
    }
}

// =======================================================================
// K5: attention v2 — two-GEMM flash per (n,h,chunk), 576 threads.
// Phase A: S[48key][144q] = K_tile(48x160) . [xe|fc2_w]^T, reg tile 3q x 4k.
// Phase B: tile-level online softmax + P.Y (thread: 1 query x 16 e).
// =======================================================================
#define W_STR  146
#define KT_STR 170
#define S_STR  146
#define XE_STR 20

__global__ __launch_bounds__(576, 1) void attn_kernel(
    const float* __restrict__ fc2_w, const float* __restrict__ fc2_b)
{
    extern __shared__ float sm[];
    float* W_sh  = sm;                       // [144][W_STR]
    float* Kt    = W_sh + 144*W_STR;         // [48][KT_STR]
    float* Yt    = Kt   + 48*KT_STR;         // [48][64]
    float* S     = Yt   + 48*64;             // [48][S_STR]
    float* xe_sh = S    + 48*S_STR;          // [144][XE_STR]
    float* bias_sh = xe_sh + 144*XE_STR;     // [144]
    int*   tq_sh  = (int*)(bias_sh + 144);   // [144]

    const int cblk = blockIdx.x;
    const int h    = blockIdx.y;
    const int n    = blockIdx.z;
    const int seg  = n*4 + h;
    const int tid  = threadIdx.x;

    if (tid < 144) {
        tq_sh[tid]   = g_perm[seg*LL + cblk*CHK + tid];
        bias_sh[tid] = fc2_b[tid]*LOG2E;
    }
    __syncthreads();
    for (int idx = tid; idx < 144*4; idx += 576) {
        int i = idx >> 2, c4 = idx & 3;
        int tokg = n*LL + tq_sh[i];
        *(float4*)&xe_sh[i*XE_STR + c4*4] = *(const float4*)&g_xe[tokg*16 + c4*4];
    }
    for (int idx = tid; idx < 144*72; idx += 576) {
        int q = idx / 72, dp = idx % 72;
        *(float2*)&W_sh[q*W_STR + dp*2] = *(const float2*)&fc2_w[q*144 + dp*2];
    }

    const int kg = tid % 12;        // key group
    const int qg = tid / 12;        // query group: queries 3qg..3qg+2
    const int qB = tid % 144;       // phase-B query
    const int eg = tid / 144;       // phase-B e-quarter

    float m = -1e30f, l = 0.f;
    ull racc[8];
#pragma unroll
    for (int r = 0; r < 8; ++r) racc[r] = 0ull;

    for (int t = 0; t < 9; ++t) {
        const int dc = t / 3;
        const int cc = (cblk + (dc == 1 ? 63 : (dc == 2 ? 1 : 0))) & 63;
        const int jr0 = (t % 3) * 48;

        __syncthreads();
        {
            const float* Ksrc = &g_K[(((size_t)(seg*64 + cc))*144 + jr0)*160];
            for (int idx = tid; idx < 48*40; idx += 576) {
                int r = idx / 40, c = idx % 40;
                float4 v = *(const float4*)&Ksrc[r*160 + c*4];
                float* dst = &Kt[r*KT_STR + c*4];
                dst[0] = v.x; dst[1] = v.y; dst[2] = v.z; dst[3] = v.w;
            }
            const float* Ysrc = &g_Y[(((size_t)(seg*64 + cc))*144 + jr0)*64];
            for (int idx = tid; idx < 48*16; idx += 576) {
                int r = idx / 16, c = idx % 16;
                *(float4*)&Yt[r*64 + c*4] = *(const float4*)&Ysrc[r*64 + c*4];
            }
        }
        __syncthreads();

        // ---- phase A: logits ----
        ull acc[12];
#pragma unroll
        for (int a = 0; a < 12; ++a) acc[a] = 0ull;

#pragma unroll
        for (int dd = 0; dd < 16; dd += 2) {
            ull q0 = *(ull*)&xe_sh[(3*qg+0)*XE_STR + dd];
            ull q1 = *(ull*)&xe_sh[(3*qg+1)*XE_STR + dd];
            ull q2 = *(ull*)&xe_sh[(3*qg+2)*XE_STR + dd];
#pragma unroll
            for (int i = 0; i < 4; ++i) {
                ull kv = *(ull*)&Kt[(kg + 12*i)*KT_STR + dd];
                acc[0*4+i] = fma2(q0, kv, acc[0*4+i]);
                acc[1*4+i] = fma2(q1, kv, acc[1*4+i]);
                acc[2*4+i] = fma2(q2, kv, acc[2*4+i]);
            }
        }
#pragma unroll 6
        for (int dd = 0; dd < 144; dd += 2) {
            ull q0 = *(ull*)&W_sh[(3*qg+0)*W_STR + dd];
            ull q1 = *(ull*)&W_sh[(3*qg+1)*W_STR + dd];
            ull q2 = *(ull*)&W_sh[(3*qg+2)*W_STR + dd];
#pragma unroll
            for (int i = 0; i < 4; ++i) {
                ull kv = *(ull*)&Kt[(kg + 12*i)*KT_STR + 16 + dd];
                acc[0*4+i] = fma2(q0, kv, acc[0*4+i]);
                acc[1*4+i] = fma2(q1, kv, acc[1*4+i]);
                acc[2*4+i] = fma2(q2, kv, acc[2*4+i]);
            }
        }
#pragma unroll
        for (int j = 0; j < 3; ++j) {
            float b = bias_sh[3*qg + j];
#pragma unroll
            for (int i = 0; i < 4; ++i) {
                float lo, hi; upk2(acc[j*4+i], lo, hi);
                S[(kg + 12*i)*S_STR + 3*qg + j] = lo + hi + b;
            }
        }
        __syncthreads();

        // ---- phase B: tile-level online softmax + P.Y ----
        float tm = -1e30f;
#pragma unroll 8
        for (int k = 0; k < 48; ++k) tm = fmaxf(tm, S[k*S_STR + qB]);
        float mn = fmaxf(m, tm);
        float al = ex2f(m - mn);
        l *= al;
        ull al2 = pk2(al, al);
#pragma unroll
        for (int r = 0; r < 8; ++r) racc[r] = mul2_(racc[r], al2);
        m = mn;
#pragma unroll 4
        for (int k = 0; k < 48; ++k) {
            float p = ex2f(S[k*S_STR + qB] - mn);
            l += p;
            ull p2 = pk2(p, p);
            const ulonglong2* yv = (const ulonglong2*)&Yt[k*64 + eg*16];
#pragma unroll
            for (int v = 0; v < 4; ++v) {
                ulonglong2 y4 = yv[v];
                racc[2*v]   = fma2(p2, y4.x, racc[2*v]);
                racc[2*v+1] = fma2(p2, y4.y, racc[2*v+1]);
            }
        }
    }

    // epilogue
    const int tq = tq_sh[qB];
    const float invl = 1.f / l;
    ull invd = pk2(invl, invl);
    float* outp = &g_ret[((size_t)seg*LL + tq)*64 + eg*16];
#pragma unroll
    for (int v = 0; v < 4; ++v) {
        ulonglong2 o;
        o.x = mul2_(racc[2*v],   invd);
        o.y = mul2_(racc[2*v+1], invd);
        *(ulonglong2*)&outp[v*4] = o;
    }
    if (eg == 0) g_bsc[seg*LL + tq] = (m + lg2f(l)) * LN2;
}

// =======================================================================
// K6: per-token softmax over heads + residual, NCHW output
// =======================================================================
__global__ __launch_bounds__(256) void final_kernel(
    const float* __restrict__ x, float* __restrict__ out)
{
    const int tg = blockIdx.x*256 + threadIdx.x;
    const int n = tg / LL, tt = tg % LL;
    float b[4];
    float mx = -1e30f;
#pragma unroll
    for (int h = 0; h < 4; ++h) {
        b[h] = g_bsc[(n*4+h)*LL + tt];
        mx = fmaxf(mx, b[h]);
    }
    float wsum = 0.f;
#pragma unroll
    for (int h = 0; h < 4; ++h) { b[h] = __expf(b[h] - mx); wsum += b[h]; }
    const float inv = 1.f / wsum;
#pragma unroll
    for (int c4 = 0; c4 < 16; ++c4) {
        float4 acc = {0.f, 0.f, 0.f, 0.f};
#pragma unroll
        for (int h = 0; h < 4; ++h) {
            float4 r = *(const float4*)&g_ret[((size_t)(n*4+h)*LL + tt)*64 + c4*4];
            float wv = b[h]*inv;
            acc.x += wv*r.x; acc.y += wv*r.y; acc.z += wv*r.z; acc.w += wv*r.w;
        }
        int c = c4*4;
        out[(n*64+c  )*LL + tt] = acc.x + x[(n*64+c  )*LL + tt];
        out[(n*64+c+1)*LL + tt] = acc.y + x[(n*64+c+1)*LL + tt];
        out[(n*64+c+2)*LL + tt] = acc.z + x[(n*64+c+2)*LL + tt];
        out[(n*64+c+3)*LL + tt] = acc.w + x[(n*64+c+3)*LL + tt];
    }
}

// =======================================================================
extern "C" void kernel_launch(void* const* d_in, const int* in_sizes, int n_in,
                              void* d_out, int out_size)
{
    const float* x     = (const float*)d_in[0];
    const float* rot   = (const float*)d_in[1];
    const float* wm    = (const float*)d_in[2];
    const float* bm    = (const float*)d_in[3];
    const float* wa    = (const float*)d_in[4];
    const float* ba    = (const float*)d_in[5];
    const float* wf    = (const float*)d_in[6];
    const float* bf    = (const float*)d_in[7];
    const float* fc1_w = (const float*)d_in[8];
    const float* fc1_b = (const float*)d_in[9];
    const float* fc2_w = (const float*)d_in[10];
    const float* fc2_b = (const float*)d_in[11];
    float* out = (float*)d_out;

    const int attn_smem = (144*W_STR + 48*KT_STR + 48*64 + 48*S_STR
                           + 144*XE_STR + 144 + 144) * 4;
    cudaFuncSetAttribute(attn_kernel,
                         cudaFuncAttributeMaxDynamicSharedMemorySize, attn_smem);

    conv_kernel <<<dim3(96, 2, 2), dim3(96, 3)>>>(x, wm, bm, wa, ba, wf, bf);
    code_kernel <<<72, 256>>>(rot);
    sort_kernel <<<8, 256>>>();
    hid_kernel  <<<576, 256>>>(fc1_w, fc1_b);
    prep_kernel <<<dim3(64, 8), 256>>>();
    attn_kernel <<<dim3(64, 4, 2), 576, attn_smem>>>(fc2_w, fc2_b);
    final_kernel<<<72, 256>>>(x, out);
}

// round 11
// speedup vs baseline: 2.8812x; 1.5024x over previous
#include <cuda_runtime.h>
#include <math.h>

#define NB 2
#define LL 9216
#define NHH 4
#define CHK 144
#define NCHK 64
#define TOKS (NB*LL)

// ---------------- static scratch ----------------
__device__ float g_xe[TOKS*16];
__device__ float g_xm[TOKS*16];
__device__ float g_ye[(size_t)TOKS*64];
__device__ float g_fe[(size_t)TOKS*64];
__device__ float g_H [(size_t)TOKS*144];
__device__ float g_F [(size_t)TOKS*144];
__device__ unsigned char g_code[NB*NHH*LL];
__device__ int   g_perm[NB*NHH*LL];
__device__ float g_bsc[NB*NHH*LL];
__device__ float g_ret[(size_t)NB*NHH*LL*64];
// pre-gathered per-(seg,chunk) K rows ([xm*L2E (16) | F (144)]) and Y rows
__device__ float g_K[(size_t)8*64*144*160];
__device__ float g_Y[(size_t)8*64*144*64];

// ---------------- packed f32x2 helpers ----------------
typedef unsigned long long ull;
__device__ __forceinline__ ull pk2(float a, float b) {
    ull r; asm("mov.b64 %0,{%1,%2};" : "=l"(r) : "f"(a), "f"(b)); return r;
}
__device__ __forceinline__ void upk2(ull v, float& a, float& b) {
    asm("mov.b64 {%0,%1},%2;" : "=f"(a), "=f"(b) : "l"(v));
}
__device__ __forceinline__ ull fma2(ull a, ull b, ull c) {
    ull d; asm("fma.rn.f32x2 %0,%1,%2,%3;" : "=l"(d) : "l"(a), "l"(b), "l"(c)); return d;
}
__device__ __forceinline__ ull mul2_(ull a, ull b) {
    ull d; asm("mul.rn.f32x2 %0,%1,%2;" : "=l"(d) : "l"(a), "l"(b)); return d;
}
__device__ __forceinline__ float ex2f(float x) {
    float y; asm("ex2.approx.ftz.f32 %0,%1;" : "=f"(y) : "f"(x)); return y;
}
__device__ __forceinline__ float lg2f(float x) {
    float y; asm("lg2.approx.ftz.f32 %0,%1;" : "=f"(y) : "f"(x)); return y;
}
#define LOG2E 1.4426950408889634f
#define LN2   0.6931471805599453f

// =======================================================================
// K1: fused 3x3 SAME conv (144 out ch) + ReLU -> xe(16), ye(64), fe(64)
// =======================================================================
__global__ __launch_bounds__(288) void conv_kernel(
    const float* __restrict__ x,
    const float* __restrict__ wm, const float* __restrict__ bm,
    const float* __restrict__ wa, const float* __restrict__ ba,
    const float* __restrict__ wf, const float* __restrict__ bf)
{
    __shared__ float in_sh[8][3][100];
    __shared__ __align__(16) float w_sh[8][9][72];

    const int y    = blockIdx.x;
    const int n    = blockIdx.y;
    const int half = blockIdx.z;
    const int xcol = threadIdx.x;
    const int lane = threadIdx.y;
    const int tid  = xcol + 96*lane;
    const int coBase = half*72;

    ull acc2[12];
#pragma unroll
    for (int m = 0; m < 12; ++m) acc2[m] = 0ull;

    for (int cb = 0; cb < 8; ++cb) {
        __syncthreads();
        for (int idx = tid; idx < 8*3*98; idx += 288) {
            int c = idx / 294, rem = idx % 294, r = rem / 98, xx = rem % 98;
            int gy = y - 1 + r, gx = xx - 1, ci = cb*8 + c;
            float v = 0.f;
            if (gy >= 0 && gy < 96 && gx >= 0 && gx < 96)
                v = x[((n*64 + ci)*96 + gy)*96 + gx];
            in_sh[c][r][xx] = v;
        }
        for (int idx = tid; idx < 8*72*9; idx += 288) {
            int c = idx / 648, rem = idx % 648, tap = rem / 72, co_l = rem % 72;
            int co = coBase + co_l, ci = cb*8 + c;
            float w;
            if (co < 16)      w = wm[( co      *64 + ci)*9 + tap];
            else if (co < 80) w = wa[((co-16)*64 + ci)*9 + tap];
            else              w = wf[((co-80)*64 + ci)*9 + tap];
            w_sh[c][tap][co_l] = w;
        }
        __syncthreads();
#pragma unroll
        for (int c = 0; c < 8; ++c) {
            ull d[9];
            d[0] = pk2(in_sh[c][0][xcol],   in_sh[c][0][xcol]);
            d[1] = pk2(in_sh[c][0][xcol+1], in_sh[c][0][xcol+1]);
            d[2] = pk2(in_sh[c][0][xcol+2], in_sh[c][0][xcol+2]);
            d[3] = pk2(in_sh[c][1][xcol],   in_sh[c][1][xcol]);
            d[4] = pk2(in_sh[c][1][xcol+1], in_sh[c][1][xcol+1]);
            d[5] = pk2(in_sh[c][1][xcol+2], in_sh[c][1][xcol+2]);
            d[6] = pk2(in_sh[c][2][xcol],   in_sh[c][2][xcol]);
            d[7] = pk2(in_sh[c][2][xcol+1], in_sh[c][2][xcol+1]);
            d[8] = pk2(in_sh[c][2][xcol+2], in_sh[c][2][xcol+2]);
#pragma unroll
            for (int tap = 0; tap < 9; ++tap) {
                const ulonglong2* wp = (const ulonglong2*)&w_sh[c][tap][lane*24];
#pragma unroll
                for (int v = 0; v < 6; ++v) {
                    ulonglong2 w4 = wp[v];
                    acc2[2*v]   = fma2(d[tap], w4.x, acc2[2*v]);
                    acc2[2*v+1] = fma2(d[tap], w4.y, acc2[2*v+1]);
                }
            }
        }
    }

    const int tok = n*LL + y*96 + xcol;
    float acc[24];
#pragma unroll
    for (int m = 0; m < 12; ++m) upk2(acc2[m], acc[2*m], acc[2*m+1]);
#pragma unroll
    for (int m = 0; m < 24; ++m) {
        int co = coBase + lane*24 + m;
        if (co < 16) {
            g_xe[tok*16 + co] = fmaxf(acc[m] + bm[co], 0.f);
        } else if (co < 80) {
            g_ye[(size_t)tok*64 + (co-16)] = fmaxf(acc[m] + ba[co-16], 0.f);
        } else {
            g_fe[(size_t)tok*64 + (co-80)] = fmaxf(acc[m] + bf[co-80], 0.f);
        }
    }
}

// =======================================================================
// K2: LSH codes + normalized xm
// =======================================================================
__global__ __launch_bounds__(256) void code_kernel(const float* __restrict__ rot)
{
    __shared__ __align__(16) float rotT[4096];
    const int tid = threadIdx.x;
    for (int idx = tid; idx < 4096; idx += 256) {
        int hi = idx >> 4, f = idx & 15;
        rotT[idx] = rot[f*256 + hi];
    }
    __syncthreads();

    const int tg = blockIdx.x*256 + tid;
    const int n = tg / LL, t = tg % LL;

    const ulonglong2* ep = (const ulonglong2*)&g_xe[tg*16];
    ull ev[8];
#pragma unroll
    for (int i = 0; i < 4; ++i) { ulonglong2 v = ep[i]; ev[2*i] = v.x; ev[2*i+1] = v.y; }

    ull ssp = 0ull;
#pragma unroll
    for (int i = 0; i < 8; ++i) ssp = fma2(ev[i], ev[i], ssp);
    float slo, shi; upk2(ssp, slo, shi);
    float inv = 1.f / fmaxf(sqrtf(slo + shi), 5e-5f);
    ull invd = pk2(inv, inv);
    ulonglong2* xmp = (ulonglong2*)&g_xm[tg*16];
#pragma unroll
    for (int i = 0; i < 4; ++i) {
        ulonglong2 o;
        o.x = mul2_(ev[2*i], invd); o.y = mul2_(ev[2*i+1], invd);
        xmp[i] = o;
    }

#pragma unroll
    for (int h = 0; h < 4; ++h) {
        float best = -1e30f; int bi = 0;
        for (int i = 0; i < 64; ++i) {
            const ull* rr = (const ull*)&rotT[(h*64+i)*16];
            ull sp = 0ull;
#pragma unroll
            for (int j = 0; j < 8; ++j) sp = fma2(ev[j], rr[j], sp);
            float a, b; upk2(sp, a, b);
            float dd = a + b;
            if (dd > best) { best = dd; bi = i; }
        }
        g_code[(n*4+h)*LL + t] = (unsigned char)bi;
    }
}

// =======================================================================
// K3: per-(n,h) stable counting sort over 64 buckets -> g_perm
// =======================================================================
__global__ __launch_bounds__(256) void sort_kernel()
{
    const int seg = blockIdx.x;
    __shared__ int hist[64];
    __shared__ int running[64];
    __shared__ int wh[8][64];
    const int tid = threadIdx.x;
    const int w = tid >> 5, ln = tid & 31;

    if (tid < 64) hist[tid] = 0;
    __syncthreads();
    const unsigned char* code = &g_code[seg*LL];
    for (int t = tid; t < LL; t += 256) atomicAdd(&hist[code[t]], 1);
    __syncthreads();
    if (tid == 0) {
        int acc = 0;
        for (int b = 0; b < 64; ++b) { running[b] = acc; acc += hist[b]; }
    }
    __syncthreads();

    for (int tile = 0; tile < 36; ++tile) {
        int t = tile*256 + tid;
        int c = code[t];
        unsigned mask = __match_any_sync(0xffffffffu, c);
        int lanerank = __popc(mask & ((1u << ln) - 1u));
        ((int*)wh)[tid] = 0; ((int*)wh)[tid + 256] = 0;
        __syncthreads();
        if (lanerank == 0) wh[w][c] = __popc(mask);
        __syncthreads();
        int r = lanerank;
        for (int w2 = 0; w2 < w; ++w2) r += wh[w2][c];
        int pos = running[c] + r;
        __syncthreads();
        if (tid < 64) {
            int s = 0;
            for (int w2 = 0; w2 < 8; ++w2) s += wh[w2][tid];
            running[tid] += s;
        }
        __syncthreads();
        g_perm[seg*LL + pos] = t;
    }
}

// =======================================================================
// K4: H = relu(fe @ fc1_w^T + fc1_b)
// =======================================================================
__global__ __launch_bounds__(256) void hid_kernel(
    const float* __restrict__ fc1_w, const float* __restrict__ fc1_b)
{
    __shared__ __align__(16) float w_sh[144][68];
    __shared__ __align__(16) float fe_sh[32][68];
    __shared__ float b_sh[144];

    const int tid = threadIdx.x;
    for (int idx = tid; idx < 144*16; idx += 256) {
        int col = idx >> 4, kq = idx & 15;
        *(float4*)&w_sh[col][kq*4] = *(const float4*)&fc1_w[col*64 + kq*4];
    }
    if (tid < 144) b_sh[tid] = fc1_b[tid];
    const int tok0 = blockIdx.x * 32;
    for (int idx = tid; idx < 32*16; idx += 256) {
        int t = idx >> 4, kq = idx & 15;
        *(float4*)&fe_sh[t][kq*4] = *(const float4*)&g_fe[(size_t)(tok0+t)*64 + kq*4];
    }
    __syncthreads();

    const int cg = tid & 15;
    const int tg = tid >> 4;
    const int c0 = cg * 9;
    const int t0 = tg * 2;

    ull acc[18];
#pragma unroll
    for (int j = 0; j < 18; ++j) acc[j] = 0ull;

#pragma unroll
    for (int kk = 0; kk < 16; ++kk) {
        ulonglong2 f0 = *(const ulonglong2*)&fe_sh[t0][kk*4];
        ulonglong2 f1 = *(const ulonglong2*)&fe_sh[t0+1][kk*4];
#pragma unroll
        for (int j = 0; j < 9; ++j) {
            ulonglong2 w4 = *(const ulonglong2*)&w_sh[c0+j][kk*4];
            acc[j]   = fma2(f0.x, w4.x, acc[j]);
            acc[j]   = fma2(f0.y, w4.y, acc[j]);
            acc[9+j] = fma2(f1.x, w4.x, acc[9+j]);
            acc[9+j] = fma2(f1.y, w4.y, acc[9+j]);
        }
    }
#pragma unroll
    for (int t = 0; t < 2; ++t)
#pragma unroll
        for (int j = 0; j < 9; ++j) {
            float lo, hi; upk2(acc[t*9+j], lo, hi);
            float s = lo + hi + b_sh[c0+j];
            g_H[(size_t)(tok0 + t0 + t)*144 + c0 + j] = fmaxf(s, 0.f);
        }
}

// =======================================================================
// K4c: F[tok][i] = LOG2E*(fc2_b[i] + sum_e fc2_w[i][e]*H[tok][e])
// GEMM 18432 x 144 x 144, block = 128 tokens, 512 threads, 1 wave (144 blocks)
// k-parity packed fma2: acc lanes hold (even-k, odd-k) partial sums.
// =======================================================================
#define FB_HS 148
#define FB_WS 150
__global__ __launch_bounds__(512, 1) void fbig_kernel(
    const float* __restrict__ fc2_w, const float* __restrict__ fc2_b)
{
    extern __shared__ float fsm[];
    float* Hs = fsm;                    // [128][FB_HS]
    float* Ws = Hs + 128*FB_HS;         // [144][FB_WS]
    float* bs = Ws + 144*FB_WS;         // [144]

    const int tid  = threadIdx.x;
    const int tok0 = blockIdx.x * 128;

    for (int idx = tid; idx < 128*36; idx += 512) {
        int t = idx / 36, kq = idx % 36;
        *(float4*)&Hs[t*FB_HS + kq*4] =
            *(const float4*)&g_H[(size_t)(tok0+t)*144 + kq*4];
    }
    for (int idx = tid; idx < 144*72; idx += 512) {
        int c = idx / 72, kp = idx % 72;
        *(float2*)&Ws[c*FB_WS + kp*2] = *(const float2*)&fc2_w[c*144 + kp*2];
    }
    if (tid < 144) bs[tid] = fc2_b[tid];
    __syncthreads();

    const int tg = tid >> 4;      // 0..31 -> 4 tokens each
    const int cg = tid & 15;      // 0..15 -> 9 cols each
    const int t0 = tg * 4;
    const int c0 = cg * 9;

    ull acc[36];
#pragma unroll
    for (int a = 0; a < 36; ++a) acc[a] = 0ull;

#pragma unroll 4
    for (int kp = 0; kp < 72; ++kp) {
        const int kk = kp*2;
        ull hv[4];
#pragma unroll
        for (int j = 0; j < 4; ++j) hv[j] = *(const ull*)&Hs[(t0+j)*FB_HS + kk];
#pragma unroll
        for (int c = 0; c < 9; ++c) {
            ull wv = *(const ull*)&Ws[(c0+c)*FB_WS + kk];
#pragma unroll
            for (int j = 0; j < 4; ++j)
                acc[j*9+c] = fma2(hv[j], wv, acc[j*9+c]);
        }
    }

#pragma unroll
    for (int j = 0; j < 4; ++j)
#pragma unroll
        for (int c = 0; c < 9; ++c) {
            float lo, hi; upk2(acc[j*9+c], lo, hi);
            g_F[(size_t)(tok0 + t0 + j)*144 + c0 + c] =
                LOG2E*(lo + hi + bs[c0+c]);
        }
}

// =======================================================================
// K4b: prep — gather per-(seg,chunk) K rows ([xm*L2E (16) | F (144)]) and Y
// =======================================================================
__global__ __launch_bounds__(256) void prep_kernel()
{
    const int chunk = blockIdx.x;
    const int seg   = blockIdx.y;
    const int n     = seg >> 2;
    const int tid   = threadIdx.x;

    __shared__ int tq_sh[144];
    if (tid < 144) tq_sh[tid] = g_perm[seg*LL + chunk*CHK + tid];
    __syncthreads();

    float* Kdst = &g_K[((size_t)(seg*64 + chunk))*144*160];
    for (int idx = tid; idx < 144*40; idx += 256) {
        int i = idx / 40, d4 = idx % 40;
        int tokg = n*LL + tq_sh[i];
        float4 v;
        if (d4 < 4) {
            v = *(const float4*)&g_xm[tokg*16 + d4*4];
            v.x *= LOG2E; v.y *= LOG2E; v.z *= LOG2E; v.w *= LOG2E;
        } else {
            v = *(const float4*)&g_F[(size_t)tokg*144 + (d4-4)*4];
        }
        *(float4*)&Kdst[i*160 + d4*4] = v;
    }
    float* Ydst = &g_Y[((size_t)(seg*64 + chunk))*144*64];
    for (int idx = tid; idx < 144*16; idx += 256) {
        int i = idx / 16, e4 = idx % 16;
        int tokg = n*LL + tq_sh[i];
        *(float4*)&Ydst[i*64 + e4*4] = *(const float4*)&g_ye[(size_t)tokg*64 + e4*4];
    }
}

// =======================================================================
// K5: attention v3 — per (n,h,chunk), 576 threads, 2 blocks/SM target.
// Stage S = F tile (logit prefill), phase A adds the 16-d xs.xmatch dot,
// phase B = tile-level online softmax + P.Y (unchanged from v2).
// =======================================================================
#define S_STR  148
#define KX_STR 18

__global__ __launch_bounds__(576, 2) void attn_kernel()
{
    extern __shared__ float sm[];
    float* S     = sm;                    // [48][S_STR]
    float* Yt    = S  + 48*S_STR;         // [48][64]
    float* Kxm   = Yt + 48*64;            // [48][KX_STR]
    float* xe_sh = Kxm + 48*KX_STR;       // [144][16]
    int*   tq_sh = (int*)(xe_sh + 144*16);

    const int cblk = blockIdx.x;
    const int h    = blockIdx.y;
    const int n    = blockIdx.z;
    const int seg  = n*4 + h;
    const int tid  = threadIdx.x;

    if (tid < 144) tq_sh[tid] = g_perm[seg*LL + cblk*CHK + tid];
    __syncthreads();
    for (int idx = tid; idx < 144*4; idx += 576) {
        int i = idx >> 2, c4 = idx & 3;
        int tokg = n*LL + tq_sh[i];
        *(float4*)&xe_sh[i*16 + c4*4] = *(const float4*)&g_xe[tokg*16 + c4*4];
    }

    const int kg = tid % 12;        // phase-A key group (4 keys)
    const int qg = tid / 12;        // phase-A query group (3 queries)
    const int qB = tid % 144;       // phase-B query
    const int eg = tid / 144;       // phase-B e-quarter

    float m = -1e30f, l = 0.f;
    ull racc[8];
#pragma unroll
    for (int r = 0; r < 8; ++r) racc[r] = 0ull;

    for (int t = 0; t < 9; ++t) {
        const int dc = t / 3;
        const int cc = (cblk + (dc == 1 ? 63 : (dc == 2 ? 1 : 0))) & 63;
        const int jr0 = (t % 3) * 48;

        __syncthreads();
        {
            const float* Ksrc = &g_K[(((size_t)(seg*64 + cc))*144 + jr0)*160];
            for (int idx = tid; idx < 48*40; idx += 576) {
                int r = idx / 40, c = idx % 40;
                float4 v = *(const float4*)&Ksrc[r*160 + c*4];
                if (c < 4) {
                    float* d = &Kxm[r*KX_STR + c*4];
                    *(float2*)d     = make_float2(v.x, v.y);
                    *(float2*)(d+2) = make_float2(v.z, v.w);
                } else {
                    *(float4*)&S[r*S_STR + (c-4)*4] = v;
                }
            }
            const float* Ysrc = &g_Y[(((size_t)(seg*64 + cc))*144 + jr0)*64];
            for (int idx = tid; idx < 48*16; idx += 576) {
                int r = idx / 16, c = idx % 16;
                *(float4*)&Yt[r*64 + c*4] = *(const float4*)&Ysrc[r*64 + c*4];
            }
        }
        __syncthreads();

        // ---- phase A: 16-d dots, add into prefetched F logits ----
        {
            ull acc[12];
#pragma unroll
            for (int a = 0; a < 12; ++a) acc[a] = 0ull;
#pragma unroll
            for (int dd = 0; dd < 16; dd += 2) {
                ull q0 = *(const ull*)&xe_sh[(3*qg+0)*16 + dd];
                ull q1 = *(const ull*)&xe_sh[(3*qg+1)*16 + dd];
                ull q2 = *(const ull*)&xe_sh[(3*qg+2)*16 + dd];
#pragma unroll
                for (int i = 0; i < 4; ++i) {
                    ull kv = *(const ull*)&Kxm[(kg + 12*i)*KX_STR + dd];
                    acc[0*4+i] = fma2(q0, kv, acc[0*4+i]);
                    acc[1*4+i] = fma2(q1, kv, acc[1*4+i]);
                    acc[2*4+i] = fma2(q2, kv, acc[2*4+i]);
                }
            }
#pragma unroll
            for (int j = 0; j < 3; ++j)
#pragma unroll
                for (int i = 0; i < 4; ++i) {
                    float lo, hi; upk2(acc[j*4+i], lo, hi);
                    S[(kg + 12*i)*S_STR + 3*qg + j] += lo + hi;
                }
        }
        __syncthreads();

        // ---- phase B: tile-level online softmax + P.Y ----
        float tm = -1e30f;
#pragma unroll 8
        for (int k = 0; k < 48; ++k) tm = fmaxf(tm, S[k*S_STR + qB]);
        float mn = fmaxf(m, tm);
        float al = ex2f(m - mn);
        l *= al;
        ull al2 = pk2(al, al);
#pragma unroll
        for (int r = 0; r < 8; ++r) racc[r] = mul2_(racc[r], al2);
        m = mn;
#pragma unroll 4
        for (int k = 0; k < 48; ++k) {
            float p = ex2f(S[k*S_STR + qB] - mn);
            l += p;
            ull p2 = pk2(p, p);
            const ulonglong2* yv = (const ulonglong2*)&Yt[k*64 + eg*16];
#pragma unroll
            for (int v = 0; v < 4; ++v) {
                ulonglong2 y4 = yv[v];
                racc[2*v]   = fma2(p2, y4.x, racc[2*v]);
                racc[2*v+1] = fma2(p2, y4.y, racc[2*v+1]);
            }
        }
    }

    // epilogue
    const int tq = tq_sh[qB];
    const float invl = 1.f / l;
    ull invd = pk2(invl, invl);
    float* outp = &g_ret[((size_t)seg*LL + tq)*64 + eg*16];
#pragma unroll
    for (int v = 0; v < 4; ++v) {
        ulonglong2 o;
        o.x = mul2_(racc[2*v],   invd);
        o.y = mul2_(racc[2*v+1], invd);
        *(ulonglong2*)&outp[v*4] = o;
    }
    if (eg == 0) g_bsc[seg*LL + tq] = (m + lg2f(l)) * LN2;
}

// =======================================================================
// K6: per-token softmax over heads + residual, NCHW output
// =======================================================================
__global__ __launch_bounds__(256) void final_kernel(
    const float* __restrict__ x, float* __restrict__ out)
{
    const int tg = blockIdx.x*256 + threadIdx.x;
    const int n = tg / LL, tt = tg % LL;
    float b[4];
    float mx = -1e30f;
#pragma unroll
    for (int h = 0; h < 4; ++h) {
        b[h] = g_bsc[(n*4+h)*LL + tt];
        mx = fmaxf(mx, b[h]);
    }
    float wsum = 0.f;
#pragma unroll
    for (int h = 0; h < 4; ++h) { b[h] = __expf(b[h] - mx); wsum += b[h]; }
    const float inv = 1.f / wsum;
#pragma unroll
    for (int c4 = 0; c4 < 16; ++c4) {
        float4 acc = {0.f, 0.f, 0.f, 0.f};
#pragma unroll
        for (int h = 0; h < 4; ++h) {
            float4 r = *(const float4*)&g_ret[((size_t)(n*4+h)*LL + tt)*64 + c4*4];
            float wv = b[h]*inv;
            acc.x += wv*r.x; acc.y += wv*r.y; acc.z += wv*r.z; acc.w += wv*r.w;
        }
        int c = c4*4;
        out[(n*64+c  )*LL + tt] = acc.x + x[(n*64+c  )*LL + tt];
        out[(n*64+c+1)*LL + tt] = acc.y + x[(n*64+c+1)*LL + tt];
        out[(n*64+c+2)*LL + tt] = acc.z + x[(n*64+c+2)*LL + tt];
        out[(n*64+c+3)*LL + tt] = acc.w + x[(n*64+c+3)*LL + tt];
    }
}

// =======================================================================
extern "C" void kernel_launch(void* const* d_in, const int* in_sizes, int n_in,
                              void* d_out, int out_size)
{
    const float* x     = (const float*)d_in[0];
    const float* rot   = (const float*)d_in[1];
    const float* wm    = (const float*)d_in[2];
    const float* bm    = (const float*)d_in[3];
    const float* wa    = (const float*)d_in[4];
    const float* ba    = (const float*)d_in[5];
    const float* wf    = (const float*)d_in[6];
    const float* bf    = (const float*)d_in[7];
    const float* fc1_w = (const float*)d_in[8];
    const float* fc1_b = (const float*)d_in[9];
    const float* fc2_w = (const float*)d_in[10];
    const float* fc2_b = (const float*)d_in[11];
    float* out = (float*)d_out;

    const int attn_smem = (48*S_STR + 48*64 + 48*KX_STR + 144*16 + 144) * 4;
    const int fbig_smem = (128*FB_HS + 144*FB_WS + 144) * 4;
    cudaFuncSetAttribute(attn_kernel,
                         cudaFuncAttributeMaxDynamicSharedMemorySize, attn_smem);
    cudaFuncSetAttribute(fbig_kernel,
                         cudaFuncAttributeMaxDynamicSharedMemorySize, fbig_smem);

    conv_kernel <<<dim3(96, 2, 2), dim3(96, 3)>>>(x, wm, bm, wa, ba, wf, bf);
    code_kernel <<<72, 256>>>(rot);
    sort_kernel <<<8, 256>>>();
    hid_kernel  <<<576, 256>>>(fc1_w, fc1_b);
    fbig_kernel <<<144, 512, fbig_smem>>>(fc2_w, fc2_b);
    prep_kernel <<<dim3(64, 8), 256>>>();
    attn_kernel <<<dim3(64, 4, 2), 576, attn_smem>>>();
    final_kernel<<<72, 256>>>(x, out);
}

// round 12
// speedup vs baseline: 2.9863x; 1.0365x over previous
#include <cuda_runtime.h>
#include <math.h>

#define NB 2
#define LL 9216
#define NHH 4
#define CHK 144
#define NCHK 64
#define TOKS (NB*LL)

// ---------------- static scratch ----------------
__device__ float g_xe[TOKS*16];
__device__ float g_xm[TOKS*16];
__device__ float g_ye[(size_t)TOKS*64];
__device__ float g_fe[(size_t)TOKS*64];
__device__ float g_H [(size_t)TOKS*144];
__device__ float g_F [(size_t)TOKS*144];
__device__ unsigned char g_code[NB*NHH*LL];
__device__ int   g_perm[NB*NHH*LL];
__device__ float g_bsc[NB*NHH*LL];
__device__ float g_ret[(size_t)NB*NHH*LL*64];
// pre-gathered per-(seg,chunk) K rows ([xm*L2E (16) | F (144)]) and Y rows
__device__ float g_K[(size_t)8*64*144*160];
__device__ float g_Y[(size_t)8*64*144*64];

// ---------------- packed f32x2 helpers ----------------
typedef unsigned long long ull;
__device__ __forceinline__ ull pk2(float a, float b) {
    ull r; asm("mov.b64 %0,{%1,%2};" : "=l"(r) : "f"(a), "f"(b)); return r;
}
__device__ __forceinline__ void upk2(ull v, float& a, float& b) {
    asm("mov.b64 {%0,%1},%2;" : "=f"(a), "=f"(b) : "l"(v));
}
__device__ __forceinline__ ull fma2(ull a, ull b, ull c) {
    ull d; asm("fma.rn.f32x2 %0,%1,%2,%3;" : "=l"(d) : "l"(a), "l"(b), "l"(c)); return d;
}
__device__ __forceinline__ ull mul2_(ull a, ull b) {
    ull d; asm("mul.rn.f32x2 %0,%1,%2;" : "=l"(d) : "l"(a), "l"(b)); return d;
}
__device__ __forceinline__ float ex2f(float x) {
    float y; asm("ex2.approx.ftz.f32 %0,%1;" : "=f"(y) : "f"(x)); return y;
}
__device__ __forceinline__ float lg2f(float x) {
    float y; asm("lg2.approx.ftz.f32 %0,%1;" : "=f"(y) : "f"(x)); return y;
}
#define LOG2E 1.4426950408889634f
#define LN2   0.6931471805599453f

// =======================================================================
// K1: fused 3x3 SAME conv (144 out ch) + ReLU -> xe(16), ye(64), fe(64)
// =======================================================================
__global__ __launch_bounds__(288) void conv_kernel(
    const float* __restrict__ x,
    const float* __restrict__ wm, const float* __restrict__ bm,
    const float* __restrict__ wa, const float* __restrict__ ba,
    const float* __restrict__ wf, const float* __restrict__ bf)
{
    __shared__ float in_sh[8][3][100];
    __shared__ __align__(16) float w_sh[8][9][72];

    const int y    = blockIdx.x;
    const int n    = blockIdx.y;
    const int half = blockIdx.z;
    const int xcol = threadIdx.x;
    const int lane = threadIdx.y;
    const int tid  = xcol + 96*lane;
    const int coBase = half*72;

    ull acc2[12];
#pragma unroll
    for (int m = 0; m < 12; ++m) acc2[m] = 0ull;

    for (int cb = 0; cb < 8; ++cb) {
        __syncthreads();
        for (int idx = tid; idx < 8*3*98; idx += 288) {
            int c = idx / 294, rem = idx % 294, r = rem / 98, xx = rem % 98;
            int gy = y - 1 + r, gx = xx - 1, ci = cb*8 + c;
            float v = 0.f;
            if (gy >= 0 && gy < 96 && gx >= 0 && gx < 96)
                v = x[((n*64 + ci)*96 + gy)*96 + gx];
            in_sh[c][r][xx] = v;
        }
        for (int idx = tid; idx < 8*72*9; idx += 288) {
            int c = idx / 648, rem = idx % 648, tap = rem / 72, co_l = rem % 72;
            int co = coBase + co_l, ci = cb*8 + c;
            float w;
            if (co < 16)      w = wm[( co      *64 + ci)*9 + tap];
            else if (co < 80) w = wa[((co-16)*64 + ci)*9 + tap];
            else              w = wf[((co-80)*64 + ci)*9 + tap];
            w_sh[c][tap][co_l] = w;
        }
        __syncthreads();
#pragma unroll
        for (int c = 0; c < 8; ++c) {
            ull d[9];
            d[0] = pk2(in_sh[c][0][xcol],   in_sh[c][0][xcol]);
            d[1] = pk2(in_sh[c][0][xcol+1], in_sh[c][0][xcol+1]);
            d[2] = pk2(in_sh[c][0][xcol+2], in_sh[c][0][xcol+2]);
            d[3] = pk2(in_sh[c][1][xcol],   in_sh[c][1][xcol]);
            d[4] = pk2(in_sh[c][1][xcol+1], in_sh[c][1][xcol+1]);
            d[5] = pk2(in_sh[c][1][xcol+2], in_sh[c][1][xcol+2]);
            d[6] = pk2(in_sh[c][2][xcol],   in_sh[c][2][xcol]);
            d[7] = pk2(in_sh[c][2][xcol+1], in_sh[c][2][xcol+1]);
            d[8] = pk2(in_sh[c][2][xcol+2], in_sh[c][2][xcol+2]);
#pragma unroll
            for (int tap = 0; tap < 9; ++tap) {
                const ulonglong2* wp = (const ulonglong2*)&w_sh[c][tap][lane*24];
#pragma unroll
                for (int v = 0; v < 6; ++v) {
                    ulonglong2 w4 = wp[v];
                    acc2[2*v]   = fma2(d[tap], w4.x, acc2[2*v]);
                    acc2[2*v+1] = fma2(d[tap], w4.y, acc2[2*v+1]);
                }
            }
        }
    }

    const int tok = n*LL + y*96 + xcol;
    float acc[24];
#pragma unroll
    for (int m = 0; m < 12; ++m) upk2(acc2[m], acc[2*m], acc[2*m+1]);
#pragma unroll
    for (int m = 0; m < 24; ++m) {
        int co = coBase + lane*24 + m;
        if (co < 16) {
            g_xe[tok*16 + co] = fmaxf(acc[m] + bm[co], 0.f);
        } else if (co < 80) {
            g_ye[(size_t)tok*64 + (co-16)] = fmaxf(acc[m] + ba[co-16], 0.f);
        } else {
            g_fe[(size_t)tok*64 + (co-80)] = fmaxf(acc[m] + bf[co-80], 0.f);
        }
    }
}

// =======================================================================
// K2: LSH codes + normalized xm
// =======================================================================
__global__ __launch_bounds__(256) void code_kernel(const float* __restrict__ rot)
{
    __shared__ __align__(16) float rotT[4096];
    const int tid = threadIdx.x;
    for (int idx = tid; idx < 4096; idx += 256) {
        int hi = idx >> 4, f = idx & 15;
        rotT[idx] = rot[f*256 + hi];
    }
    __syncthreads();

    const int tg = blockIdx.x*256 + tid;
    const int n = tg / LL, t = tg % LL;

    const ulonglong2* ep = (const ulonglong2*)&g_xe[tg*16];
    ull ev[8];
#pragma unroll
    for (int i = 0; i < 4; ++i) { ulonglong2 v = ep[i]; ev[2*i] = v.x; ev[2*i+1] = v.y; }

    ull ssp = 0ull;
#pragma unroll
    for (int i = 0; i < 8; ++i) ssp = fma2(ev[i], ev[i], ssp);
    float slo, shi; upk2(ssp, slo, shi);
    float inv = 1.f / fmaxf(sqrtf(slo + shi), 5e-5f);
    ull invd = pk2(inv, inv);
    ulonglong2* xmp = (ulonglong2*)&g_xm[tg*16];
#pragma unroll
    for (int i = 0; i < 4; ++i) {
        ulonglong2 o;
        o.x = mul2_(ev[2*i], invd); o.y = mul2_(ev[2*i+1], invd);
        xmp[i] = o;
    }

#pragma unroll
    for (int h = 0; h < 4; ++h) {
        float best = -1e30f; int bi = 0;
        for (int i = 0; i < 64; ++i) {
            const ull* rr = (const ull*)&rotT[(h*64+i)*16];
            ull sp = 0ull;
#pragma unroll
            for (int j = 0; j < 8; ++j) sp = fma2(ev[j], rr[j], sp);
            float a, b; upk2(sp, a, b);
            float dd = a + b;
            if (dd > best) { best = dd; bi = i; }
        }
        g_code[(n*4+h)*LL + t] = (unsigned char)bi;
    }
}

// =======================================================================
// K3: per-(n,h) stable counting sort over 64 buckets -> g_perm
// =======================================================================
__global__ __launch_bounds__(256) void sort_kernel()
{
    const int seg = blockIdx.x;
    __shared__ int hist[64];
    __shared__ int running[64];
    __shared__ int wh[8][64];
    const int tid = threadIdx.x;
    const int w = tid >> 5, ln = tid & 31;

    if (tid < 64) hist[tid] = 0;
    __syncthreads();
    const unsigned char* code = &g_code[seg*LL];
    for (int t = tid; t < LL; t += 256) atomicAdd(&hist[code[t]], 1);
    __syncthreads();
    if (tid == 0) {
        int acc = 0;
        for (int b = 0; b < 64; ++b) { running[b] = acc; acc += hist[b]; }
    }
    __syncthreads();

    for (int tile = 0; tile < 36; ++tile) {
        int t = tile*256 + tid;
        int c = code[t];
        unsigned mask = __match_any_sync(0xffffffffu, c);
        int lanerank = __popc(mask & ((1u << ln) - 1u));
        ((int*)wh)[tid] = 0; ((int*)wh)[tid + 256] = 0;
        __syncthreads();
        if (lanerank == 0) wh[w][c] = __popc(mask);
        __syncthreads();
        int r = lanerank;
        for (int w2 = 0; w2 < w; ++w2) r += wh[w2][c];
        int pos = running[c] + r;
        __syncthreads();
        if (tid < 64) {
            int s = 0;
            for (int w2 = 0; w2 < 8; ++w2) s += wh[w2][tid];
            running[tid] += s;
        }
        __syncthreads();
        g_perm[seg*LL + pos] = t;
    }
}

// =======================================================================
// K4: H = relu(fe @ fc1_w^T + fc1_b)
// =======================================================================
__global__ __launch_bounds__(256) void hid_kernel(
    const float* __restrict__ fc1_w, const float* __restrict__ fc1_b)
{
    __shared__ __align__(16) float w_sh[144][68];
    __shared__ __align__(16) float fe_sh[32][68];
    __shared__ float b_sh[144];

    const int tid = threadIdx.x;
    for (int idx = tid; idx < 144*16; idx += 256) {
        int col = idx >> 4, kq = idx & 15;
        *(float4*)&w_sh[col][kq*4] = *(const float4*)&fc1_w[col*64 + kq*4];
    }
    if (tid < 144) b_sh[tid] = fc1_b[tid];
    const int tok0 = blockIdx.x * 32;
    for (int idx = tid; idx < 32*16; idx += 256) {
        int t = idx >> 4, kq = idx & 15;
        *(float4*)&fe_sh[t][kq*4] = *(const float4*)&g_fe[(size_t)(tok0+t)*64 + kq*4];
    }
    __syncthreads();

    const int cg = tid & 15;
    const int tg = tid >> 4;
    const int c0 = cg * 9;
    const int t0 = tg * 2;

    ull acc[18];
#pragma unroll
    for (int j = 0; j < 18; ++j) acc[j] = 0ull;

#pragma unroll
    for (int kk = 0; kk < 16; ++kk) {
        ulonglong2 f0 = *(const ulonglong2*)&fe_sh[t0][kk*4];
        ulonglong2 f1 = *(const ulonglong2*)&fe_sh[t0+1][kk*4];
#pragma unroll
        for (int j = 0; j < 9; ++j) {
            ulonglong2 w4 = *(const ulonglong2*)&w_sh[c0+j][kk*4];
            acc[j]   = fma2(f0.x, w4.x, acc[j]);
            acc[j]   = fma2(f0.y, w4.y, acc[j]);
            acc[9+j] = fma2(f1.x, w4.x, acc[9+j]);
            acc[9+j] = fma2(f1.y, w4.y, acc[9+j]);
        }
    }
#pragma unroll
    for (int t = 0; t < 2; ++t)
#pragma unroll
        for (int j = 0; j < 9; ++j) {
            float lo, hi; upk2(acc[t*9+j], lo, hi);
            float s = lo + hi + b_sh[c0+j];
            g_H[(size_t)(tok0 + t0 + t)*144 + c0 + j] = fmaxf(s, 0.f);
        }
}

// =======================================================================
// K4c: F[tok][i] = LOG2E*(fc2_b[i] + sum_e fc2_w[i][e]*H[tok][e])
// =======================================================================
#define FB_HS 148
#define FB_WS 150
__global__ __launch_bounds__(512, 1) void fbig_kernel(
    const float* __restrict__ fc2_w, const float* __restrict__ fc2_b)
{
    extern __shared__ float fsm[];
    float* Hs = fsm;                    // [128][FB_HS]
    float* Ws = Hs + 128*FB_HS;         // [144][FB_WS]
    float* bs = Ws + 144*FB_WS;         // [144]

    const int tid  = threadIdx.x;
    const int tok0 = blockIdx.x * 128;

    for (int idx = tid; idx < 128*36; idx += 512) {
        int t = idx / 36, kq = idx % 36;
        *(float4*)&Hs[t*FB_HS + kq*4] =
            *(const float4*)&g_H[(size_t)(tok0+t)*144 + kq*4];
    }
    for (int idx = tid; idx < 144*72; idx += 512) {
        int c = idx / 72, kp = idx % 72;
        *(float2*)&Ws[c*FB_WS + kp*2] = *(const float2*)&fc2_w[c*144 + kp*2];
    }
    if (tid < 144) bs[tid] = fc2_b[tid];
    __syncthreads();

    const int tg = tid >> 4;
    const int cg = tid & 15;
    const int t0 = tg * 4;
    const int c0 = cg * 9;

    ull acc[36];
#pragma unroll
    for (int a = 0; a < 36; ++a) acc[a] = 0ull;

#pragma unroll 4
    for (int kp = 0; kp < 72; ++kp) {
        const int kk = kp*2;
        ull hv[4];
#pragma unroll
        for (int j = 0; j < 4; ++j) hv[j] = *(const ull*)&Hs[(t0+j)*FB_HS + kk];
#pragma unroll
        for (int c = 0; c < 9; ++c) {
            ull wv = *(const ull*)&Ws[(c0+c)*FB_WS + kk];
#pragma unroll
            for (int j = 0; j < 4; ++j)
                acc[j*9+c] = fma2(hv[j], wv, acc[j*9+c]);
        }
    }

#pragma unroll
    for (int j = 0; j < 4; ++j)
#pragma unroll
        for (int c = 0; c < 9; ++c) {
            float lo, hi; upk2(acc[j*9+c], lo, hi);
            g_F[(size_t)(tok0 + t0 + j)*144 + c0 + c] =
                LOG2E*(lo + hi + bs[c0+c]);
        }
}

// =======================================================================
// K4b: prep — gather per-(seg,chunk) K rows ([xm*L2E (16) | F (144)]) and Y
// =======================================================================
__global__ __launch_bounds__(256) void prep_kernel()
{
    const int chunk = blockIdx.x;
    const int seg   = blockIdx.y;
    const int n     = seg >> 2;
    const int tid   = threadIdx.x;

    __shared__ int tq_sh[144];
    if (tid < 144) tq_sh[tid] = g_perm[seg*LL + chunk*CHK + tid];
    __syncthreads();

    float* Kdst = &g_K[((size_t)(seg*64 + chunk))*144*160];
    for (int idx = tid; idx < 144*40; idx += 256) {
        int i = idx / 40, d4 = idx % 40;
        int tokg = n*LL + tq_sh[i];
        float4 v;
        if (d4 < 4) {
            v = *(const float4*)&g_xm[tokg*16 + d4*4];
            v.x *= LOG2E; v.y *= LOG2E; v.z *= LOG2E; v.w *= LOG2E;
        } else {
            v = *(const float4*)&g_F[(size_t)tokg*144 + (d4-4)*4];
        }
        *(float4*)&Kdst[i*160 + d4*4] = v;
    }
    float* Ydst = &g_Y[((size_t)(seg*64 + chunk))*144*64];
    for (int idx = tid; idx < 144*16; idx += 256) {
        int i = idx / 16, e4 = idx % 16;
        int tokg = n*LL + tq_sh[i];
        *(float4*)&Ydst[i*64 + e4*4] = *(const float4*)&g_ye[(size_t)tokg*64 + e4*4];
    }
}

// =======================================================================
// K5: attention v4 — per (n,h,chunk), 576 threads.
// Phase A: 16-d dots added to prefetched F logits (S[k][q]).
// Phase B1: per-(q, k-quarter) online softmax bookkeeping; P materialized
//           in smem as duplicated (p,p) ull pairs; per-quarter l.
// Phase B2: register-tiled GEMM P(144x48) . Y(48x64), thread = 4q x 4e.
// =======================================================================
#define S_STR  148
#define KX_STR 18

__global__ __launch_bounds__(576, 2) void attn_kernel()
{
    extern __shared__ __align__(16) char smraw[];
    ull*   P2    = (ull*)smraw;                    // [48][144] dup pairs
    float* S     = (float*)(P2 + 48*144);          // [48][S_STR]
    float* Yt    = S  + 48*S_STR;                  // [48][64]
    float* Kxm   = Yt + 48*64;                     // [48][KX_STR]
    float* xe_sh = Kxm + 48*KX_STR;                // [144][16]
    float* Mt    = xe_sh + 144*16;                 // [4][144]
    float* alS   = Mt + 4*144;                     // [144]
    int*   tq_sh = (int*)(alS + 144);              // [144]

    const int cblk = blockIdx.x;
    const int h    = blockIdx.y;
    const int n    = blockIdx.z;
    const int seg  = n*4 + h;
    const int tid  = threadIdx.x;

    if (tid < 144) tq_sh[tid] = g_perm[seg*LL + cblk*CHK + tid];
    __syncthreads();
    for (int idx = tid; idx < 144*4; idx += 576) {
        int i = idx >> 2, c4 = idx & 3;
        int tokg = n*LL + tq_sh[i];
        *(float4*)&xe_sh[i*16 + c4*4] = *(const float4*)&g_xe[tokg*16 + c4*4];
    }

    const int kg = tid % 12;        // phase-A key group (4 keys)
    const int qg = tid / 12;        // phase-A query group (3 queries)
    const int q1 = tid % 144;       // phase-B1 query
    const int kg1 = tid / 144;      // phase-B1 key quarter (12 keys)
    const int qg2 = tid >> 4;       // phase-B2 query group (4 queries)
    const int eg2 = tid & 15;       // phase-B2 e group (4 floats)
    const int q0B = qg2 * 4;

    float m = -1e30f, l = 0.f;
    ull racc[8];
#pragma unroll
    for (int r = 0; r < 8; ++r) racc[r] = 0ull;

    for (int t = 0; t < 9; ++t) {
        const int dc = t / 3;
        const int cc = (cblk + (dc == 1 ? 63 : (dc == 2 ? 1 : 0))) & 63;
        const int jr0 = (t % 3) * 48;

        __syncthreads();
        {
            const float* Ksrc = &g_K[(((size_t)(seg*64 + cc))*144 + jr0)*160];
            for (int idx = tid; idx < 48*40; idx += 576) {
                int r = idx / 40, c = idx % 40;
                float4 v = *(const float4*)&Ksrc[r*160 + c*4];
                if (c < 4) {
                    float* d = &Kxm[r*KX_STR + c*4];
                    *(float2*)d     = make_float2(v.x, v.y);
                    *(float2*)(d+2) = make_float2(v.z, v.w);
                } else {
                    *(float4*)&S[r*S_STR + (c-4)*4] = v;
                }
            }
            const float* Ysrc = &g_Y[(((size_t)(seg*64 + cc))*144 + jr0)*64];
            for (int idx = tid; idx < 48*16; idx += 576) {
                int r = idx / 16, c = idx % 16;
                *(float4*)&Yt[r*64 + c*4] = *(const float4*)&Ysrc[r*64 + c*4];
            }
        }
        __syncthreads();

        // ---- phase A: 16-d dots, add into prefetched F logits ----
        {
            ull acc[12];
#pragma unroll
            for (int a = 0; a < 12; ++a) acc[a] = 0ull;
#pragma unroll
            for (int dd = 0; dd < 16; dd += 2) {
                ull qa = *(const ull*)&xe_sh[(3*qg+0)*16 + dd];
                ull qb = *(const ull*)&xe_sh[(3*qg+1)*16 + dd];
                ull qc = *(const ull*)&xe_sh[(3*qg+2)*16 + dd];
#pragma unroll
                for (int i = 0; i < 4; ++i) {
                    ull kv = *(const ull*)&Kxm[(kg + 12*i)*KX_STR + dd];
                    acc[0*4+i] = fma2(qa, kv, acc[0*4+i]);
                    acc[1*4+i] = fma2(qb, kv, acc[1*4+i]);
                    acc[2*4+i] = fma2(qc, kv, acc[2*4+i]);
                }
            }
#pragma unroll
            for (int j = 0; j < 3; ++j)
#pragma unroll
                for (int i = 0; i < 4; ++i) {
                    float lo, hi; upk2(acc[j*4+i], lo, hi);
                    S[(kg + 12*i)*S_STR + 3*qg + j] += lo + hi;
                }
        }
        __syncthreads();

        // ---- phase B1: tile max + P materialization + l quarters ----
        {
            float tm = -1e30f;
#pragma unroll
            for (int j = 0; j < 12; ++j)
                tm = fmaxf(tm, S[(kg1*12 + j)*S_STR + q1]);
            Mt[kg1*144 + q1] = tm;
        }
        __syncthreads();
        {
            float tmax = fmaxf(fmaxf(Mt[q1], Mt[144+q1]),
                               fmaxf(Mt[288+q1], Mt[432+q1]));
            float mn = fmaxf(m, tmax);
            float al = ex2f(m - mn);
            m = mn;
            l *= al;
            if (kg1 == 0) alS[q1] = al;
#pragma unroll
            for (int j = 0; j < 12; ++j) {
                int k = kg1*12 + j;
                float p = ex2f(S[k*S_STR + q1] - mn);
                l += p;
                P2[k*144 + q1] = pk2(p, p);
            }
        }
        __syncthreads();

        // ---- phase B2: register-tiled P.Y GEMM (4q x 4e per thread) ----
        {
            float a0 = alS[q0B], a1 = alS[q0B+1], a2 = alS[q0B+2], a3 = alS[q0B+3];
            racc[0] = mul2_(racc[0], pk2(a0,a0)); racc[1] = mul2_(racc[1], pk2(a0,a0));
            racc[2] = mul2_(racc[2], pk2(a1,a1)); racc[3] = mul2_(racc[3], pk2(a1,a1));
            racc[4] = mul2_(racc[4], pk2(a2,a2)); racc[5] = mul2_(racc[5], pk2(a2,a2));
            racc[6] = mul2_(racc[6], pk2(a3,a3)); racc[7] = mul2_(racc[7], pk2(a3,a3));
#pragma unroll 4
            for (int k = 0; k < 48; ++k) {
                ull p0 = P2[k*144 + q0B];
                ull p1 = P2[k*144 + q0B+1];
                ull pq2 = P2[k*144 + q0B+2];
                ull p3 = P2[k*144 + q0B+3];
                ulonglong2 yv = *(const ulonglong2*)&Yt[k*64 + eg2*4];
                racc[0] = fma2(p0,  yv.x, racc[0]); racc[1] = fma2(p0,  yv.y, racc[1]);
                racc[2] = fma2(p1,  yv.x, racc[2]); racc[3] = fma2(p1,  yv.y, racc[3]);
                racc[4] = fma2(pq2, yv.x, racc[4]); racc[5] = fma2(pq2, yv.y, racc[5]);
                racc[6] = fma2(p3,  yv.x, racc[6]); racc[7] = fma2(p3,  yv.y, racc[7]);
            }
        }
    }

    // ---- epilogue ----
    __syncthreads();
    Mt[kg1*144 + q1] = l;          // per-quarter l
    __syncthreads();
    if (tid < 144) {
        float lt = Mt[tid] + Mt[144+tid] + Mt[288+tid] + Mt[432+tid];
        alS[tid] = 1.f / lt;       // reuse alS as inv-l
        g_bsc[seg*LL + tq_sh[tid]] = (m + lg2f(lt)) * LN2;  // tid==q1, kg1==0 holds m
    }
    __syncthreads();
    {
        float i0 = alS[q0B], i1 = alS[q0B+1], i2 = alS[q0B+2], i3 = alS[q0B+3];
        ull iv0 = pk2(i0,i0), iv1 = pk2(i1,i1), iv2 = pk2(i2,i2), iv3 = pk2(i3,i3);
        const int ebase = eg2*4;
#pragma unroll
        for (int j = 0; j < 4; ++j) {
            ull ivj = (j==0) ? iv0 : (j==1) ? iv1 : (j==2) ? iv2 : iv3;
            int tq = tq_sh[q0B + j];
            ulonglong2 o;
            o.x = mul2_(racc[2*j],   ivj);
            o.y = mul2_(racc[2*j+1], ivj);
            *(ulonglong2*)&g_ret[((size_t)seg*LL + tq)*64 + ebase] = o;
        }
    }
}

// =======================================================================
// K6: per-token softmax over heads + residual, NCHW output
// =======================================================================
__global__ __launch_bounds__(256) void final_kernel(
    const float* __restrict__ x, float* __restrict__ out)
{
    const int tg = blockIdx.x*256 + threadIdx.x;
    const int n = tg / LL, tt = tg % LL;
    float b[4];
    float mx = -1e30f;
#pragma unroll
    for (int h = 0; h < 4; ++h) {
        b[h] = g_bsc[(n*4+h)*LL + tt];
        mx = fmaxf(mx, b[h]);
    }
    float wsum = 0.f;
#pragma unroll
    for (int h = 0; h < 4; ++h) { b[h] = __expf(b[h] - mx); wsum += b[h]; }
    const float inv = 1.f / wsum;
#pragma unroll
    for (int c4 = 0; c4 < 16; ++c4) {
        float4 acc = {0.f, 0.f, 0.f, 0.f};
#pragma unroll
        for (int h = 0; h < 4; ++h) {
            float4 r = *(const float4*)&g_ret[((size_t)(n*4+h)*LL + tt)*64 + c4*4];
            float wv = b[h]*inv;
            acc.x += wv*r.x; acc.y += wv*r.y; acc.z += wv*r.z; acc.w += wv*r.w;
        }
        int c = c4*4;
        out[(n*64+c  )*LL + tt] = acc.x + x[(n*64+c  )*LL + tt];
        out[(n*64+c+1)*LL + tt] = acc.y + x[(n*64+c+1)*LL + tt];
        out[(n*64+c+2)*LL + tt] = acc.z + x[(n*64+c+2)*LL + tt];
        out[(n*64+c+3)*LL + tt] = acc.w + x[(n*64+c+3)*LL + tt];
    }
}

// =======================================================================
extern "C" void kernel_launch(void* const* d_in, const int* in_sizes, int n_in,
                              void* d_out, int out_size)
{
    const float* x     = (const float*)d_in[0];
    const float* rot   = (const float*)d_in[1];
    const float* wm    = (const float*)d_in[2];
    const float* bm    = (const float*)d_in[3];
    const float* wa    = (const float*)d_in[4];
    const float* ba    = (const float*)d_in[5];
    const float* wf    = (const float*)d_in[6];
    const float* bf    = (const float*)d_in[7];
    const float* fc1_w = (const float*)d_in[8];
    const float* fc1_b = (const float*)d_in[9];
    const float* fc2_w = (const float*)d_in[10];
    const float* fc2_b = (const float*)d_in[11];
    float* out = (float*)d_out;

    const int attn_smem = 48*144*8
        + (48*S_STR + 48*64 + 48*KX_STR + 144*16 + 4*144 + 144) * 4
        + 144*4;
    const int fbig_smem = (128*FB_HS + 144*FB_WS + 144) * 4;
    cudaFuncSetAttribute(attn_kernel,
                         cudaFuncAttributeMaxDynamicSharedMemorySize, attn_smem);
    cudaFuncSetAttribute(fbig_kernel,
                         cudaFuncAttributeMaxDynamicSharedMemorySize, fbig_smem);

    conv_kernel <<<dim3(96, 2, 2), dim3(96, 3)>>>(x, wm, bm, wa, ba, wf, bf);
    code_kernel <<<72, 256>>>(rot);
    sort_kernel <<<8, 256>>>();
    hid_kernel  <<<576, 256>>>(fc1_w, fc1_b);
    fbig_kernel <<<144, 512, fbig_smem>>>(fc2_w, fc2_b);
    prep_kernel <<<dim3(64, 8), 256>>>();
    attn_kernel <<<dim3(64, 4, 2), 576, attn_smem>>>();
    final_kernel<<<72, 256>>>(x, out);
}